// round 9
// baseline (speedup 1.0000x reference)
#include <cuda_runtime.h>
#include <cuda_bf16.h>
#include <cuda_fp16.h>

#define NN 50000
#define EE 1600000
#define DD 128
#define GG 512
#define NB 196          // ceil(NN/256)
#define CBLK 391        // ceil(NN/128)

// ---------------- scratch (static device globals; no allocation) ----------------
__device__ float g_agg[NN * DD];             // fp32 mean-aggregated features
__device__ __half g_xh[NN * DD];             // fp16 copy of current layer input (gather payload)
__device__ __nv_bfloat16 g_Bh[3 * 128 * 256];
__device__ __nv_bfloat16 g_Bl[3 * 128 * 256];
__device__ float g_x1[NN * DD];
__device__ float g_x2[NN * DD];
__device__ float g_invdeg[NN];
__device__ int   g_deg[NN];
__device__ int   g_rowptr[NN];
__device__ int   g_cursor[NN];
__device__ int   g_src[EE];
__device__ int   g_dst[EE];
__device__ int   g_esrc[EE];
__device__ int   g_batch[NN];
__device__ float g_acc[GG];
__device__ float g_cnt[GG];
__device__ int   g_blocksum[NB];
__device__ int   g_is64;

// ---------------- init: zero scratch + dtype probe (one launch) ----------------
__global__ void init_kernel(const void* __restrict__ ei) {
    int i = blockIdx.x * blockDim.x + threadIdx.x;
    if (i < NN) g_deg[i] = 0;
    if (i < GG) { g_acc[i] = 0.f; g_cnt[i] = 0.f; }
    if (i == 0) {
        const long long* p = (const long long*)ei;
        int ok = 1;
#pragma unroll 1
        for (int j = 0; j < 64; j++) {
            long long v = p[j];
            if (v < 0 || v >= NN) ok = 0;
        }
        g_is64 = ok;
    }
}

// ---------------- convert_all: edges (+deg histogram), x->fp16, weights->hi/lo ----------------
__global__ void convert_all_kernel(const void* __restrict__ ei, const float* __restrict__ x,
                                   const float* __restrict__ Wl0, const float* __restrict__ Wr0,
                                   const float* __restrict__ Wl1, const float* __restrict__ Wr1,
                                   const float* __restrict__ Wl2, const float* __restrict__ Wr2) {
    const int gs = gridDim.x * blockDim.x;
    const int t0 = blockIdx.x * blockDim.x + threadIdx.x;
    const int is64 = g_is64;
    const long long* p64 = (const long long*)ei;
    const int*       p32 = (const int*)ei;
    // 1. edges
    for (int i = t0; i < EE; i += gs) {
        int s, d;
        if (is64) { s = (int)p64[i]; d = (int)p64[EE + i]; }
        else      { s = p32[i];      d = p32[EE + i]; }
        g_src[i] = s;
        g_dst[i] = d;
        atomicAdd(&g_deg[d], 1);
    }
    // 2. x -> fp16
    for (int i = t0; i < NN * DD / 2; i += gs) {
        float2 v = ((const float2*)x)[i];
        ((__half2*)g_xh)[i] = __floats2half2_rn(v.x, v.y);
    }
    // 3. weights -> hi/lo bf16
    for (int i = t0; i < 3 * 128 * 256; i += gs) {
        int l = i >> 15;
        int j = i & 32767;
        int n = j >> 8, k = j & 255;
        const float* Wl = (l == 0) ? Wl0 : (l == 1 ? Wl1 : Wl2);
        const float* Wr = (l == 0) ? Wr0 : (l == 1 ? Wr1 : Wr2);
        float v = (k < 128) ? Wl[n * 128 + k] : Wr[n * 128 + (k - 128)];
        __nv_bfloat16 h = __float2bfloat16(v);
        __nv_bfloat16 lo = __float2bfloat16(v - __bfloat162float(h));
        g_Bh[i] = h;
        g_Bl[i] = lo;
    }
}

// ---------------- scan for CSR (+batch conversion folded into part1) ----------------
__global__ void scan_part1_kernel(const void* __restrict__ b) {
    __shared__ int sh[256];
    __shared__ float scnt[GG];
    const int t = threadIdx.x;
    const int i = blockIdx.x * 256 + t;
    int v = (i < NN) ? g_deg[i] : 0;
    sh[t] = v;
    scnt[t] = 0.f; scnt[t + 256] = 0.f;
    __syncthreads();
    if (i < NN) {
        const int is64 = g_is64;
        int g = is64 ? (int)((const long long*)b)[i] : ((const int*)b)[i];
        g_batch[i] = g;
        atomicAdd(&scnt[g], 1.f);
    }
    __syncthreads();
    if (scnt[t] != 0.f) atomicAdd(&g_cnt[t], scnt[t]);
    if (scnt[t + 256] != 0.f) atomicAdd(&g_cnt[t + 256], scnt[t + 256]);
    for (int o = 128; o; o >>= 1) {
        if (t < o) sh[t] += sh[t + o];
        __syncthreads();
    }
    if (t == 0) g_blocksum[blockIdx.x] = sh[0];
}

// scan3 with scan2 absorbed: every block redundantly scans the 196 block sums
__global__ void scan_part3_kernel() {
    __shared__ int sb[256];
    __shared__ int sh[256];
    int t = threadIdx.x;
    // redundant exclusive scan of block sums
    sb[t] = (t < NB) ? g_blocksum[t] : 0;
    __syncthreads();
    for (int o = 1; o < 256; o <<= 1) {
        int v = (t >= o) ? sb[t - o] : 0;
        __syncthreads();
        sb[t] += v;
        __syncthreads();
    }
    int blockoff = (blockIdx.x == 0) ? 0 : sb[blockIdx.x - 1];
    // in-block inclusive scan of deg
    int i = blockIdx.x * 256 + t;
    int v = (i < NN) ? g_deg[i] : 0;
    sh[t] = v;
    __syncthreads();
    for (int o = 1; o < 256; o <<= 1) {
        int u = (t >= o) ? sh[t - o] : 0;
        __syncthreads();
        sh[t] += u;
        __syncthreads();
    }
    if (i < NN) {
        int excl = sh[t] - v + blockoff;
        g_rowptr[i] = excl;
        g_cursor[i] = excl;
        g_invdeg[i] = 1.f / fmaxf((float)v, 1.f);
    }
}

__global__ void place_edges_kernel() {
    for (int i = blockIdx.x * blockDim.x + threadIdx.x; i < EE; i += gridDim.x * blockDim.x) {
        int d = g_dst[i];
        int pos = atomicAdd(&g_cursor[d], 1);
        g_esrc[pos] = g_src[i];
    }
}

// ---------------- gather mean -> g_agg: 2 edges per LDG.128, shfl'd index window ----------------
__global__ __launch_bounds__(256) void gather_kernel() {
    const unsigned FULL = 0xffffffffu;
    int node = (blockIdx.x * 256 + threadIdx.x) >> 5;
    if (node >= NN) return;
    const int lane = threadIdx.x & 31;
    const int half = lane >> 4;       // 0: even edge of pair, 1: odd
    const int sub  = lane & 15;       // 16B chunk within 256B row
    const int beg = g_rowptr[node];
    const int end = beg + g_deg[node];

    float a0 = 0.f, a1 = 0.f, a2 = 0.f, a3 = 0.f, a4 = 0.f, a5 = 0.f, a6 = 0.f, a7 = 0.f;

#pragma unroll 1
    for (int w = beg; w < end; w += 32) {
        int widx = (w + lane < end) ? g_esrc[w + lane] : 0;
        const int m = min(32, end - w);
        int it = 0;
#pragma unroll 1
        for (; it + 4 <= m; it += 4) {
            int sA = __shfl_sync(FULL, widx, it + half);
            int sB = __shfl_sync(FULL, widx, it + 2 + half);
            uint4 v0 = __ldg((const uint4*)g_xh + (size_t)sA * 16 + sub);
            uint4 v1 = __ldg((const uint4*)g_xh + (size_t)sB * 16 + sub);
            float2 p;
            p = __half22float2(*(__half2*)&v0.x); a0 += p.x; a1 += p.y;
            p = __half22float2(*(__half2*)&v0.y); a2 += p.x; a3 += p.y;
            p = __half22float2(*(__half2*)&v0.z); a4 += p.x; a5 += p.y;
            p = __half22float2(*(__half2*)&v0.w); a6 += p.x; a7 += p.y;
            p = __half22float2(*(__half2*)&v1.x); a0 += p.x; a1 += p.y;
            p = __half22float2(*(__half2*)&v1.y); a2 += p.x; a3 += p.y;
            p = __half22float2(*(__half2*)&v1.z); a4 += p.x; a5 += p.y;
            p = __half22float2(*(__half2*)&v1.w); a6 += p.x; a7 += p.y;
        }
#pragma unroll 1
        for (; it + 2 <= m; it += 2) {
            int sA = __shfl_sync(FULL, widx, it + half);
            uint4 v0 = __ldg((const uint4*)g_xh + (size_t)sA * 16 + sub);
            float2 p;
            p = __half22float2(*(__half2*)&v0.x); a0 += p.x; a1 += p.y;
            p = __half22float2(*(__half2*)&v0.y); a2 += p.x; a3 += p.y;
            p = __half22float2(*(__half2*)&v0.z); a4 += p.x; a5 += p.y;
            p = __half22float2(*(__half2*)&v0.w); a6 += p.x; a7 += p.y;
        }
        if (it < m) {   // single leftover edge: lanes with half==0 cover the row
            int sA = __shfl_sync(FULL, widx, it);
            if (half == 0) {
                uint4 v0 = __ldg((const uint4*)g_xh + (size_t)sA * 16 + sub);
                float2 p;
                p = __half22float2(*(__half2*)&v0.x); a0 += p.x; a1 += p.y;
                p = __half22float2(*(__half2*)&v0.y); a2 += p.x; a3 += p.y;
                p = __half22float2(*(__half2*)&v0.z); a4 += p.x; a5 += p.y;
                p = __half22float2(*(__half2*)&v0.w); a6 += p.x; a7 += p.y;
            }
        }
    }
    // combine odd/even partial sums (lane L <-> lane L+16 hold same columns)
    a0 += __shfl_xor_sync(FULL, a0, 16);
    a1 += __shfl_xor_sync(FULL, a1, 16);
    a2 += __shfl_xor_sync(FULL, a2, 16);
    a3 += __shfl_xor_sync(FULL, a3, 16);
    a4 += __shfl_xor_sync(FULL, a4, 16);
    a5 += __shfl_xor_sync(FULL, a5, 16);
    a6 += __shfl_xor_sync(FULL, a6, 16);
    a7 += __shfl_xor_sync(FULL, a7, 16);
    if (half == 0) {
        float inv = g_invdeg[node];
        float4* dst = (float4*)g_agg + (size_t)node * 32 + sub * 2;
        dst[0] = make_float4(a0 * inv, a1 * inv, a2 * inv, a3 * inv);
        dst[1] = make_float4(a4 * inv, a5 * inv, a6 * inv, a7 * inv);
    }
}

// ---------------- combine via mma.sync bf16 split: Y = relu([agg|x] @ B^T + b) ----------------
#define MMA16816(d, a, b0_, b1_) \
    asm volatile("mma.sync.aligned.m16n8k16.row.col.f32.bf16.bf16.f32 " \
                 "{%0,%1,%2,%3},{%4,%5,%6,%7},{%8,%9},{%0,%1,%2,%3};" \
                 : "+f"(d[0]), "+f"(d[1]), "+f"(d[2]), "+f"(d[3]) \
                 : "r"(a[0]), "r"(a[1]), "r"(a[2]), "r"(a[3]), "r"(b0_), "r"(b1_))

__global__ __launch_bounds__(256, 2) void combine_kernel(
    int layer, const float* __restrict__ bias, const float* __restrict__ xext,
    int xsel, int osel, const float* __restrict__ fcw, int do_pool)
{
    const float* __restrict__ xpart = (xsel == 0) ? xext : (xsel == 1 ? g_x1 : g_x2);
    float* __restrict__ y = (osel == 1) ? g_x1 : g_x2;
    const __nv_bfloat16* __restrict__ Bh = g_Bh + layer * 128 * 256;
    const __nv_bfloat16* __restrict__ Bl = g_Bl + layer * 128 * 256;

    __shared__ __nv_bfloat16 sAh[128 * 36];
    __shared__ __nv_bfloat16 sAl[128 * 36];
    __shared__ __nv_bfloat16 sBh[128 * 36];
    __shared__ __nv_bfloat16 sBl[128 * 36];
    __shared__ float sdot[128];

    const int tid = threadIdx.x;
    const int lane = tid & 31;
    const int warp = tid >> 5;
    const int wm = warp & 3;
    const int wn = warp >> 2;
    const int row0 = blockIdx.x * 128;
    const int gr = lane >> 2;
    const int tg2 = (lane & 3) * 2;

    if (do_pool && tid < 128) sdot[tid] = 0.f;

    float acc[2][8][4];
#pragma unroll
    for (int mt = 0; mt < 2; mt++)
#pragma unroll
        for (int nt = 0; nt < 8; nt++)
#pragma unroll
            for (int q = 0; q < 4; q++) acc[mt][nt][q] = 0.f;

#pragma unroll 1
    for (int c = 0; c < 8; c++) {
        const int k0 = c * 32;
        const bool from_x = (k0 >= 128);
        const float* __restrict__ Asrc = from_x ? xpart : g_agg;
        const int kb = from_x ? (k0 - 128) : k0;
#pragma unroll
        for (int it = 0; it < 4; it++) {
            int s = tid + it * 256;         // 0..1023
            int r = s >> 3;                 // 0..127
            int c4 = (s & 7) * 4;           // 0..28
            int grow = row0 + r; if (grow >= NN) grow = NN - 1;
            float4 v = *(const float4*)(Asrc + (size_t)grow * DD + kb + c4);
            __nv_bfloat16 h0 = __float2bfloat16(v.x);
            __nv_bfloat16 h1 = __float2bfloat16(v.y);
            __nv_bfloat16 h2 = __float2bfloat16(v.z);
            __nv_bfloat16 h3 = __float2bfloat16(v.w);
            __nv_bfloat16 l0 = __float2bfloat16(v.x - __bfloat162float(h0));
            __nv_bfloat16 l1 = __float2bfloat16(v.y - __bfloat162float(h1));
            __nv_bfloat16 l2 = __float2bfloat16(v.z - __bfloat162float(h2));
            __nv_bfloat16 l3 = __float2bfloat16(v.w - __bfloat162float(h3));
            uint2 hh, ll;
            hh.x = (unsigned int)__bfloat16_as_ushort(h0) | ((unsigned int)__bfloat16_as_ushort(h1) << 16);
            hh.y = (unsigned int)__bfloat16_as_ushort(h2) | ((unsigned int)__bfloat16_as_ushort(h3) << 16);
            ll.x = (unsigned int)__bfloat16_as_ushort(l0) | ((unsigned int)__bfloat16_as_ushort(l1) << 16);
            ll.y = (unsigned int)__bfloat16_as_ushort(l2) | ((unsigned int)__bfloat16_as_ushort(l3) << 16);
            *(uint2*)&sAh[r * 36 + c4] = hh;
            *(uint2*)&sAl[r * 36 + c4] = ll;
            *(uint2*)&sBh[r * 36 + c4] = *(const uint2*)&Bh[r * 256 + k0 + c4];
            *(uint2*)&sBl[r * 36 + c4] = *(const uint2*)&Bl[r * 256 + k0 + c4];
        }
        __syncthreads();

#pragma unroll
        for (int kk = 0; kk < 32; kk += 16) {
            unsigned int ah[2][4], al[2][4];
#pragma unroll
            for (int mt = 0; mt < 2; mt++) {
                int rb = wm * 32 + mt * 16;
                ah[mt][0] = *(const unsigned int*)&sAh[(rb + gr) * 36 + kk + tg2];
                ah[mt][1] = *(const unsigned int*)&sAh[(rb + gr + 8) * 36 + kk + tg2];
                ah[mt][2] = *(const unsigned int*)&sAh[(rb + gr) * 36 + kk + tg2 + 8];
                ah[mt][3] = *(const unsigned int*)&sAh[(rb + gr + 8) * 36 + kk + tg2 + 8];
                al[mt][0] = *(const unsigned int*)&sAl[(rb + gr) * 36 + kk + tg2];
                al[mt][1] = *(const unsigned int*)&sAl[(rb + gr + 8) * 36 + kk + tg2];
                al[mt][2] = *(const unsigned int*)&sAl[(rb + gr) * 36 + kk + tg2 + 8];
                al[mt][3] = *(const unsigned int*)&sAl[(rb + gr + 8) * 36 + kk + tg2 + 8];
            }
#pragma unroll
            for (int nt = 0; nt < 8; nt++) {
                int nb = wn * 64 + nt * 8 + gr;
                unsigned int bh0 = *(const unsigned int*)&sBh[nb * 36 + kk + tg2];
                unsigned int bh1 = *(const unsigned int*)&sBh[nb * 36 + kk + tg2 + 8];
                unsigned int bl0 = *(const unsigned int*)&sBl[nb * 36 + kk + tg2];
                unsigned int bl1 = *(const unsigned int*)&sBl[nb * 36 + kk + tg2 + 8];
#pragma unroll
                for (int mt = 0; mt < 2; mt++) {
                    MMA16816(acc[mt][nt], ah[mt], bh0, bh1);
                    MMA16816(acc[mt][nt], ah[mt], bl0, bl1);
                    MMA16816(acc[mt][nt], al[mt], bh0, bh1);
                }
            }
        }
        __syncthreads();
    }

    // ---- epilogue ----
    if (!do_pool) {
#pragma unroll
        for (int mt = 0; mt < 2; mt++) {
#pragma unroll
            for (int nt = 0; nt < 8; nt++) {
                int col = wn * 64 + nt * 8 + tg2;
                float b0 = bias[col], b1 = bias[col + 1];
#pragma unroll
                for (int half = 0; half < 2; half++) {
                    int row = row0 + wm * 32 + mt * 16 + gr + half * 8;
                    if (row >= NN) continue;
                    float v0 = fmaxf(acc[mt][nt][half * 2 + 0] + b0, 0.f);
                    float v1 = fmaxf(acc[mt][nt][half * 2 + 1] + b1, 0.f);
                    *(float2*)&y[(size_t)row * DD + col] = make_float2(v0, v1);
                    *(__half2*)&g_xh[(size_t)row * DD + col] = __floats2half2_rn(v0, v1);
                }
            }
        }
    } else {
#pragma unroll
        for (int mt = 0; mt < 2; mt++) {
#pragma unroll
            for (int nt = 0; nt < 8; nt++) {
                int col = wn * 64 + nt * 8 + tg2;
                float b0 = bias[col], b1 = bias[col + 1];
                float w0 = fcw[col], w1 = fcw[col + 1];
#pragma unroll
                for (int half = 0; half < 2; half++) {
                    int lr = wm * 32 + mt * 16 + gr + half * 8;
                    float v0 = fmaxf(acc[mt][nt][half * 2 + 0] + b0, 0.f);
                    float v1 = fmaxf(acc[mt][nt][half * 2 + 1] + b1, 0.f);
                    atomicAdd(&sdot[lr], v0 * w0 + v1 * w1);
                }
            }
        }
        __syncthreads();
        if (tid < 128) {
            int grow = row0 + tid;
            if (grow < NN) atomicAdd(&g_acc[g_batch[grow]], sdot[tid]);
        }
    }
}

__global__ void final_kernel(float* __restrict__ out, const float* __restrict__ fcb) {
    int g = blockIdx.x * blockDim.x + threadIdx.x;
    if (g < GG) out[g] = g_acc[g] / fmaxf(g_cnt[g], 1.f) + fcb[0];
}

// ---------------- launch ----------------
extern "C" void kernel_launch(void* const* d_in, const int* in_sizes, int n_in,
                              void* d_out, int out_size) {
    const float* x     = (const float*)d_in[0];
    const void*  ei    = d_in[1];
    const void*  batch = d_in[2];
    const float* Wl[3] = {(const float*)d_in[3], (const float*)d_in[6], (const float*)d_in[9]};
    const float* bb[3] = {(const float*)d_in[4], (const float*)d_in[7], (const float*)d_in[10]};
    const float* Wr[3] = {(const float*)d_in[5], (const float*)d_in[8], (const float*)d_in[11]};
    const float* fcw = (const float*)d_in[12];
    const float* fcb = (const float*)d_in[13];
    float* out = (float*)d_out;

    // prep (5 launches)
    init_kernel<<<NB, 256>>>(ei);
    convert_all_kernel<<<2048, 256>>>(ei, x, Wl[0], Wr[0], Wl[1], Wr[1], Wl[2], Wr[2]);
    scan_part1_kernel<<<NB, 256>>>(batch);
    scan_part3_kernel<<<NB, 256>>>();
    place_edges_kernel<<<4096, 256>>>();

    const int gather_blocks = (NN * 32 + 255) / 256;

    // layer 0: x -> g_x1 (+g_xh)
    gather_kernel<<<gather_blocks, 256>>>();
    combine_kernel<<<CBLK, 256>>>(0, bb[0], x, 0, 1, fcw, 0);
    // layer 1: g_x1 -> g_x2 (+g_xh)
    gather_kernel<<<gather_blocks, 256>>>();
    combine_kernel<<<CBLK, 256>>>(1, bb[1], x, 1, 2, fcw, 0);
    // layer 2: g_x2 -> pooled dots (no y)
    gather_kernel<<<gather_blocks, 256>>>();
    combine_kernel<<<CBLK, 256>>>(2, bb[2], x, 2, 0, fcw, 1);

    final_kernel<<<(GG + 255) / 256, 256>>>(out, fcb);
}

// round 10
// speedup vs baseline: 1.0541x; 1.0541x over previous
#include <cuda_runtime.h>
#include <cuda_bf16.h>
#include <cuda_fp16.h>

#define NN 50000
#define EE 1600000
#define DD 128
#define GG 512
#define NB 196          // ceil(NN/256)
#define CBLK 391        // ceil(NN/128)

// ---------------- scratch (static device globals; no allocation) ----------------
__device__ float g_agg[NN * DD];             // fp32 mean-aggregated features
__device__ __half g_xh[NN * DD];             // fp16 copy of current layer input (gather payload)
__device__ __nv_bfloat16 g_Bh[3 * 128 * 256];
__device__ __nv_bfloat16 g_Bl[3 * 128 * 256];
__device__ float g_x1[NN * DD];
__device__ float g_x2[NN * DD];
__device__ float g_invdeg[NN];
__device__ int   g_deg[NN];
__device__ int   g_rowptr[NN];
__device__ int   g_cursor[NN];
__device__ int   g_src[EE];
__device__ int   g_dst[EE];
__device__ int   g_esrc[EE];
__device__ int   g_batch[NN];
__device__ float g_acc[GG];
__device__ float g_cnt[GG];
__device__ int   g_blocksum[NB];
__device__ int   g_is64;

// ---------------- init: zero scratch + dtype probe (one launch) ----------------
__global__ void init_kernel(const void* __restrict__ ei) {
    int i = blockIdx.x * blockDim.x + threadIdx.x;
    if (i < NN) g_deg[i] = 0;
    if (i < GG) { g_acc[i] = 0.f; g_cnt[i] = 0.f; }
    if (i == 0) {
        const long long* p = (const long long*)ei;
        int ok = 1;
#pragma unroll 1
        for (int j = 0; j < 64; j++) {
            long long v = p[j];
            if (v < 0 || v >= NN) ok = 0;
        }
        g_is64 = ok;
    }
}

// ---------------- convert_all: edges (+deg histogram), x->fp16, weights->hi/lo ----------------
__global__ void convert_all_kernel(const void* __restrict__ ei, const float* __restrict__ x,
                                   const float* __restrict__ Wl0, const float* __restrict__ Wr0,
                                   const float* __restrict__ Wl1, const float* __restrict__ Wr1,
                                   const float* __restrict__ Wl2, const float* __restrict__ Wr2) {
    const int gs = gridDim.x * blockDim.x;
    const int t0 = blockIdx.x * blockDim.x + threadIdx.x;
    const int is64 = g_is64;
    const long long* p64 = (const long long*)ei;
    const int*       p32 = (const int*)ei;
    // 1. edges
    for (int i = t0; i < EE; i += gs) {
        int s, d;
        if (is64) { s = (int)p64[i]; d = (int)p64[EE + i]; }
        else      { s = p32[i];      d = p32[EE + i]; }
        g_src[i] = s;
        g_dst[i] = d;
        atomicAdd(&g_deg[d], 1);
    }
    // 2. x -> fp16
    for (int i = t0; i < NN * DD / 2; i += gs) {
        float2 v = ((const float2*)x)[i];
        ((__half2*)g_xh)[i] = __floats2half2_rn(v.x, v.y);
    }
    // 3. weights -> hi/lo bf16
    for (int i = t0; i < 3 * 128 * 256; i += gs) {
        int l = i >> 15;
        int j = i & 32767;
        int n = j >> 8, k = j & 255;
        const float* Wl = (l == 0) ? Wl0 : (l == 1 ? Wl1 : Wl2);
        const float* Wr = (l == 0) ? Wr0 : (l == 1 ? Wr1 : Wr2);
        float v = (k < 128) ? Wl[n * 128 + k] : Wr[n * 128 + (k - 128)];
        __nv_bfloat16 h = __float2bfloat16(v);
        __nv_bfloat16 lo = __float2bfloat16(v - __bfloat162float(h));
        g_Bh[i] = h;
        g_Bl[i] = lo;
    }
}

// ---------------- scan for CSR (+batch conversion folded into part1) ----------------
__global__ void scan_part1_kernel(const void* __restrict__ b) {
    __shared__ int sh[256];
    __shared__ float scnt[GG];
    const int t = threadIdx.x;
    const int i = blockIdx.x * 256 + t;
    int v = (i < NN) ? g_deg[i] : 0;
    sh[t] = v;
    scnt[t] = 0.f; scnt[t + 256] = 0.f;
    __syncthreads();
    if (i < NN) {
        const int is64 = g_is64;
        int g = is64 ? (int)((const long long*)b)[i] : ((const int*)b)[i];
        g_batch[i] = g;
        atomicAdd(&scnt[g], 1.f);
    }
    __syncthreads();
    if (scnt[t] != 0.f) atomicAdd(&g_cnt[t], scnt[t]);
    if (scnt[t + 256] != 0.f) atomicAdd(&g_cnt[t + 256], scnt[t + 256]);
    for (int o = 128; o; o >>= 1) {
        if (t < o) sh[t] += sh[t + o];
        __syncthreads();
    }
    if (t == 0) g_blocksum[blockIdx.x] = sh[0];
}

// scan3 with scan2 absorbed: every block redundantly scans the 196 block sums
__global__ void scan_part3_kernel() {
    __shared__ int sb[256];
    __shared__ int sh[256];
    int t = threadIdx.x;
    sb[t] = (t < NB) ? g_blocksum[t] : 0;
    __syncthreads();
    for (int o = 1; o < 256; o <<= 1) {
        int v = (t >= o) ? sb[t - o] : 0;
        __syncthreads();
        sb[t] += v;
        __syncthreads();
    }
    int blockoff = (blockIdx.x == 0) ? 0 : sb[blockIdx.x - 1];
    int i = blockIdx.x * 256 + t;
    int v = (i < NN) ? g_deg[i] : 0;
    sh[t] = v;
    __syncthreads();
    for (int o = 1; o < 256; o <<= 1) {
        int u = (t >= o) ? sh[t - o] : 0;
        __syncthreads();
        sh[t] += u;
        __syncthreads();
    }
    if (i < NN) {
        int excl = sh[t] - v + blockoff;
        g_rowptr[i] = excl;
        g_cursor[i] = excl;
        g_invdeg[i] = 1.f / fmaxf((float)v, 1.f);
    }
}

__global__ void place_edges_kernel() {
    for (int i = blockIdx.x * blockDim.x + threadIdx.x; i < EE; i += gridDim.x * blockDim.x) {
        int d = g_dst[i];
        int pos = atomicAdd(&g_cursor[d], 1);
        g_esrc[pos] = g_src[i];
    }
}

// ---------------- gather mean -> g_agg (fp32): warp per node, fp16 rows, MLP 8 ----------------
__global__ __launch_bounds__(256) void gather_kernel() {
    int warp = (blockIdx.x * 256 + threadIdx.x) >> 5;
    if (warp >= NN) return;
    int lane = threadIdx.x & 31;
    int beg = g_rowptr[warp];
    int end = beg + g_deg[warp];

    float4 acc = make_float4(0.f, 0.f, 0.f, 0.f);
    int e = beg;
#pragma unroll 1
    for (; e + 8 <= end; e += 8) {
        int s0 = g_esrc[e + 0];
        int s1 = g_esrc[e + 1];
        int s2 = g_esrc[e + 2];
        int s3 = g_esrc[e + 3];
        int s4 = g_esrc[e + 4];
        int s5 = g_esrc[e + 5];
        int s6 = g_esrc[e + 6];
        int s7 = g_esrc[e + 7];
        uint2 u0 = __ldg((const uint2*)g_xh + (size_t)s0 * 32 + lane);
        uint2 u1 = __ldg((const uint2*)g_xh + (size_t)s1 * 32 + lane);
        uint2 u2 = __ldg((const uint2*)g_xh + (size_t)s2 * 32 + lane);
        uint2 u3 = __ldg((const uint2*)g_xh + (size_t)s3 * 32 + lane);
        uint2 u4 = __ldg((const uint2*)g_xh + (size_t)s4 * 32 + lane);
        uint2 u5 = __ldg((const uint2*)g_xh + (size_t)s5 * 32 + lane);
        uint2 u6 = __ldg((const uint2*)g_xh + (size_t)s6 * 32 + lane);
        uint2 u7 = __ldg((const uint2*)g_xh + (size_t)s7 * 32 + lane);
#pragma unroll
        for (int q = 0; q < 8; q++) {
            uint2 u = (q == 0) ? u0 : (q == 1) ? u1 : (q == 2) ? u2 : (q == 3) ? u3 :
                      (q == 4) ? u4 : (q == 5) ? u5 : (q == 6) ? u6 : u7;
            float2 p0 = __half22float2(*(__half2*)&u.x);
            float2 p1 = __half22float2(*(__half2*)&u.y);
            acc.x += p0.x; acc.y += p0.y; acc.z += p1.x; acc.w += p1.y;
        }
    }
#pragma unroll 1
    for (; e < end; e++) {
        int s = g_esrc[e];
        uint2 u = __ldg((const uint2*)g_xh + (size_t)s * 32 + lane);
        float2 p0 = __half22float2(*(__half2*)&u.x);
        float2 p1 = __half22float2(*(__half2*)&u.y);
        acc.x += p0.x; acc.y += p0.y; acc.z += p1.x; acc.w += p1.y;
    }
    float inv = g_invdeg[warp];
    acc.x *= inv; acc.y *= inv; acc.z *= inv; acc.w *= inv;
    ((float4*)g_agg)[(size_t)warp * 32 + lane] = acc;
}

// ---------------- combine via mma.sync bf16 split: Y = relu([agg|x] @ B^T + b) ----------------
#define MMA16816(d, a, b0_, b1_) \
    asm volatile("mma.sync.aligned.m16n8k16.row.col.f32.bf16.bf16.f32 " \
                 "{%0,%1,%2,%3},{%4,%5,%6,%7},{%8,%9},{%0,%1,%2,%3};" \
                 : "+f"(d[0]), "+f"(d[1]), "+f"(d[2]), "+f"(d[3]) \
                 : "r"(a[0]), "r"(a[1]), "r"(a[2]), "r"(a[3]), "r"(b0_), "r"(b1_))

__global__ __launch_bounds__(256, 2) void combine_kernel(
    int layer, const float* __restrict__ bias, const float* __restrict__ xext,
    int xsel, int osel, const float* __restrict__ fcw, int do_pool)
{
    const float* __restrict__ xpart = (xsel == 0) ? xext : (xsel == 1 ? g_x1 : g_x2);
    float* __restrict__ y = (osel == 1) ? g_x1 : g_x2;
    const __nv_bfloat16* __restrict__ Bh = g_Bh + layer * 128 * 256;
    const __nv_bfloat16* __restrict__ Bl = g_Bl + layer * 128 * 256;

    __shared__ __nv_bfloat16 sAh[128 * 36];
    __shared__ __nv_bfloat16 sAl[128 * 36];
    __shared__ __nv_bfloat16 sBh[128 * 36];
    __shared__ __nv_bfloat16 sBl[128 * 36];
    __shared__ float sdot[128];

    const int tid = threadIdx.x;
    const int lane = tid & 31;
    const int warp = tid >> 5;
    const int wm = warp & 3;
    const int wn = warp >> 2;
    const int row0 = blockIdx.x * 128;
    const int gr = lane >> 2;
    const int tg2 = (lane & 3) * 2;

    if (do_pool && tid < 128) sdot[tid] = 0.f;

    float acc[2][8][4];
#pragma unroll
    for (int mt = 0; mt < 2; mt++)
#pragma unroll
        for (int nt = 0; nt < 8; nt++)
#pragma unroll
            for (int q = 0; q < 4; q++) acc[mt][nt][q] = 0.f;

#pragma unroll 1
    for (int c = 0; c < 8; c++) {
        const int k0 = c * 32;
        const bool from_x = (k0 >= 128);
        const float* __restrict__ Asrc = from_x ? xpart : g_agg;
        const int kb = from_x ? (k0 - 128) : k0;
#pragma unroll
        for (int it = 0; it < 4; it++) {
            int s = tid + it * 256;         // 0..1023
            int r = s >> 3;                 // 0..127
            int c4 = (s & 7) * 4;           // 0..28
            int grow = row0 + r; if (grow >= NN) grow = NN - 1;
            float4 v = *(const float4*)(Asrc + (size_t)grow * DD + kb + c4);
            __nv_bfloat16 h0 = __float2bfloat16(v.x);
            __nv_bfloat16 h1 = __float2bfloat16(v.y);
            __nv_bfloat16 h2 = __float2bfloat16(v.z);
            __nv_bfloat16 h3 = __float2bfloat16(v.w);
            __nv_bfloat16 l0 = __float2bfloat16(v.x - __bfloat162float(h0));
            __nv_bfloat16 l1 = __float2bfloat16(v.y - __bfloat162float(h1));
            __nv_bfloat16 l2 = __float2bfloat16(v.z - __bfloat162float(h2));
            __nv_bfloat16 l3 = __float2bfloat16(v.w - __bfloat162float(h3));
            uint2 hh, ll;
            hh.x = (unsigned int)__bfloat16_as_ushort(h0) | ((unsigned int)__bfloat16_as_ushort(h1) << 16);
            hh.y = (unsigned int)__bfloat16_as_ushort(h2) | ((unsigned int)__bfloat16_as_ushort(h3) << 16);
            ll.x = (unsigned int)__bfloat16_as_ushort(l0) | ((unsigned int)__bfloat16_as_ushort(l1) << 16);
            ll.y = (unsigned int)__bfloat16_as_ushort(l2) | ((unsigned int)__bfloat16_as_ushort(l3) << 16);
            *(uint2*)&sAh[r * 36 + c4] = hh;
            *(uint2*)&sAl[r * 36 + c4] = ll;
            *(uint2*)&sBh[r * 36 + c4] = *(const uint2*)&Bh[r * 256 + k0 + c4];
            *(uint2*)&sBl[r * 36 + c4] = *(const uint2*)&Bl[r * 256 + k0 + c4];
        }
        __syncthreads();

#pragma unroll
        for (int kk = 0; kk < 32; kk += 16) {
            unsigned int ah[2][4], al[2][4];
#pragma unroll
            for (int mt = 0; mt < 2; mt++) {
                int rb = wm * 32 + mt * 16;
                ah[mt][0] = *(const unsigned int*)&sAh[(rb + gr) * 36 + kk + tg2];
                ah[mt][1] = *(const unsigned int*)&sAh[(rb + gr + 8) * 36 + kk + tg2];
                ah[mt][2] = *(const unsigned int*)&sAh[(rb + gr) * 36 + kk + tg2 + 8];
                ah[mt][3] = *(const unsigned int*)&sAh[(rb + gr + 8) * 36 + kk + tg2 + 8];
                al[mt][0] = *(const unsigned int*)&sAl[(rb + gr) * 36 + kk + tg2];
                al[mt][1] = *(const unsigned int*)&sAl[(rb + gr + 8) * 36 + kk + tg2];
                al[mt][2] = *(const unsigned int*)&sAl[(rb + gr) * 36 + kk + tg2 + 8];
                al[mt][3] = *(const unsigned int*)&sAl[(rb + gr + 8) * 36 + kk + tg2 + 8];
            }
#pragma unroll
            for (int nt = 0; nt < 8; nt++) {
                int nb = wn * 64 + nt * 8 + gr;
                unsigned int bh0 = *(const unsigned int*)&sBh[nb * 36 + kk + tg2];
                unsigned int bh1 = *(const unsigned int*)&sBh[nb * 36 + kk + tg2 + 8];
                unsigned int bl0 = *(const unsigned int*)&sBl[nb * 36 + kk + tg2];
                unsigned int bl1 = *(const unsigned int*)&sBl[nb * 36 + kk + tg2 + 8];
#pragma unroll
                for (int mt = 0; mt < 2; mt++) {
                    MMA16816(acc[mt][nt], ah[mt], bh0, bh1);
                    MMA16816(acc[mt][nt], ah[mt], bl0, bl1);
                    MMA16816(acc[mt][nt], al[mt], bh0, bh1);
                }
            }
        }
        __syncthreads();
    }

    // ---- epilogue ----
    if (!do_pool) {
#pragma unroll
        for (int mt = 0; mt < 2; mt++) {
#pragma unroll
            for (int nt = 0; nt < 8; nt++) {
                int col = wn * 64 + nt * 8 + tg2;
                float b0 = bias[col], b1 = bias[col + 1];
#pragma unroll
                for (int half = 0; half < 2; half++) {
                    int row = row0 + wm * 32 + mt * 16 + gr + half * 8;
                    if (row >= NN) continue;
                    float v0 = fmaxf(acc[mt][nt][half * 2 + 0] + b0, 0.f);
                    float v1 = fmaxf(acc[mt][nt][half * 2 + 1] + b1, 0.f);
                    *(float2*)&y[(size_t)row * DD + col] = make_float2(v0, v1);
                    *(__half2*)&g_xh[(size_t)row * DD + col] = __floats2half2_rn(v0, v1);
                }
            }
        }
    } else {
#pragma unroll
        for (int mt = 0; mt < 2; mt++) {
#pragma unroll
            for (int nt = 0; nt < 8; nt++) {
                int col = wn * 64 + nt * 8 + tg2;
                float b0 = bias[col], b1 = bias[col + 1];
                float w0 = fcw[col], w1 = fcw[col + 1];
#pragma unroll
                for (int half = 0; half < 2; half++) {
                    int lr = wm * 32 + mt * 16 + gr + half * 8;
                    float v0 = fmaxf(acc[mt][nt][half * 2 + 0] + b0, 0.f);
                    float v1 = fmaxf(acc[mt][nt][half * 2 + 1] + b1, 0.f);
                    atomicAdd(&sdot[lr], v0 * w0 + v1 * w1);
                }
            }
        }
        __syncthreads();
        if (tid < 128) {
            int grow = row0 + tid;
            if (grow < NN) atomicAdd(&g_acc[g_batch[grow]], sdot[tid]);
        }
    }
}

__global__ void final_kernel(float* __restrict__ out, const float* __restrict__ fcb) {
    int g = blockIdx.x * blockDim.x + threadIdx.x;
    if (g < GG) out[g] = g_acc[g] / fmaxf(g_cnt[g], 1.f) + fcb[0];
}

// ---------------- launch ----------------
extern "C" void kernel_launch(void* const* d_in, const int* in_sizes, int n_in,
                              void* d_out, int out_size) {
    const float* x     = (const float*)d_in[0];
    const void*  ei    = d_in[1];
    const void*  batch = d_in[2];
    const float* Wl[3] = {(const float*)d_in[3], (const float*)d_in[6], (const float*)d_in[9]};
    const float* bb[3] = {(const float*)d_in[4], (const float*)d_in[7], (const float*)d_in[10]};
    const float* Wr[3] = {(const float*)d_in[5], (const float*)d_in[8], (const float*)d_in[11]};
    const float* fcw = (const float*)d_in[12];
    const float* fcb = (const float*)d_in[13];
    float* out = (float*)d_out;

    // prep (5 launches)
    init_kernel<<<NB, 256>>>(ei);
    convert_all_kernel<<<2048, 256>>>(ei, x, Wl[0], Wr[0], Wl[1], Wr[1], Wl[2], Wr[2]);
    scan_part1_kernel<<<NB, 256>>>(batch);
    scan_part3_kernel<<<NB, 256>>>();
    place_edges_kernel<<<4096, 256>>>();

    const int gather_blocks = (NN * 32 + 255) / 256;

    // layer 0: x -> g_x1 (+g_xh)
    gather_kernel<<<gather_blocks, 256>>>();
    combine_kernel<<<CBLK, 256>>>(0, bb[0], x, 0, 1, fcw, 0);
    // layer 1: g_x1 -> g_x2 (+g_xh)
    gather_kernel<<<gather_blocks, 256>>>();
    combine_kernel<<<CBLK, 256>>>(1, bb[1], x, 1, 2, fcw, 0);
    // layer 2: g_x2 -> pooled dots (no y)
    gather_kernel<<<gather_blocks, 256>>>();
    combine_kernel<<<CBLK, 256>>>(2, bb[2], x, 2, 0, fcw, 1);

    final_kernel<<<(GG + 255) / 256, 256>>>(out, fcb);
}

// round 11
// speedup vs baseline: 1.2835x; 1.2176x over previous
#include <cuda_runtime.h>
#include <cuda_fp16.h>

#define NN 50000
#define EE 1600000
#define DD 128
#define GG 512
#define NB 196          // ceil(NN/256)
#define CBLK 391        // ceil(NN/128)

// ---------------- scratch (static device globals; no allocation) ----------------
__device__ __half g_aggh[NN * DD];           // fp16 mean-aggregated features
__device__ __half g_xh[NN * DD];             // fp16 current layer features (gather payload + x-part)
__device__ __half g_Bh[3 * 128 * 256];       // W fp16 hi
__device__ __half g_Bl[3 * 128 * 256];       // W fp16 residual
__device__ float g_invdeg[NN];
__device__ int   g_deg[NN];
__device__ int   g_rowptr[NN];
__device__ int   g_cursor[NN];
__device__ int   g_src[EE];
__device__ int   g_dst[EE];
__device__ int   g_esrc[EE];
__device__ int   g_batch[NN];
__device__ float g_acc[GG];
__device__ float g_cnt[GG];
__device__ int   g_blocksum[NB];
__device__ int   g_is64;

// ---------------- init: zero scratch + dtype probe (one launch) ----------------
__global__ void init_kernel(const void* __restrict__ ei) {
    int i = blockIdx.x * blockDim.x + threadIdx.x;
    if (i < NN) g_deg[i] = 0;
    if (i < GG) { g_acc[i] = 0.f; g_cnt[i] = 0.f; }
    if (i == 0) {
        const long long* p = (const long long*)ei;
        int ok = 1;
#pragma unroll 1
        for (int j = 0; j < 64; j++) {
            long long v = p[j];
            if (v < 0 || v >= NN) ok = 0;
        }
        g_is64 = ok;
    }
}

// ---------------- convert_all: edges (+deg histogram), x->fp16, weights->hi/lo fp16 ----------------
__global__ void convert_all_kernel(const void* __restrict__ ei, const float* __restrict__ x,
                                   const float* __restrict__ Wl0, const float* __restrict__ Wr0,
                                   const float* __restrict__ Wl1, const float* __restrict__ Wr1,
                                   const float* __restrict__ Wl2, const float* __restrict__ Wr2) {
    const int gs = gridDim.x * blockDim.x;
    const int t0 = blockIdx.x * blockDim.x + threadIdx.x;
    const int is64 = g_is64;
    const long long* p64 = (const long long*)ei;
    const int*       p32 = (const int*)ei;
    // 1. edges
    for (int i = t0; i < EE; i += gs) {
        int s, d;
        if (is64) { s = (int)p64[i]; d = (int)p64[EE + i]; }
        else      { s = p32[i];      d = p32[EE + i]; }
        g_src[i] = s;
        g_dst[i] = d;
        atomicAdd(&g_deg[d], 1);
    }
    // 2. x -> fp16
    for (int i = t0; i < NN * DD / 2; i += gs) {
        float2 v = ((const float2*)x)[i];
        ((__half2*)g_xh)[i] = __floats2half2_rn(v.x, v.y);
    }
    // 3. weights -> hi/lo fp16
    for (int i = t0; i < 3 * 128 * 256; i += gs) {
        int l = i >> 15;
        int j = i & 32767;
        int n = j >> 8, k = j & 255;
        const float* Wl = (l == 0) ? Wl0 : (l == 1 ? Wl1 : Wl2);
        const float* Wr = (l == 0) ? Wr0 : (l == 1 ? Wr1 : Wr2);
        float v = (k < 128) ? Wl[n * 128 + k] : Wr[n * 128 + (k - 128)];
        __half h = __float2half_rn(v);
        __half lo = __float2half_rn(v - __half2float(h));
        g_Bh[i] = h;
        g_Bl[i] = lo;
    }
}

// ---------------- scan for CSR (+batch conversion folded into part1) ----------------
__global__ void scan_part1_kernel(const void* __restrict__ b) {
    __shared__ int sh[256];
    __shared__ float scnt[GG];
    const int t = threadIdx.x;
    const int i = blockIdx.x * 256 + t;
    int v = (i < NN) ? g_deg[i] : 0;
    sh[t] = v;
    scnt[t] = 0.f; scnt[t + 256] = 0.f;
    __syncthreads();
    if (i < NN) {
        const int is64 = g_is64;
        int g = is64 ? (int)((const long long*)b)[i] : ((const int*)b)[i];
        g_batch[i] = g;
        atomicAdd(&scnt[g], 1.f);
    }
    __syncthreads();
    if (scnt[t] != 0.f) atomicAdd(&g_cnt[t], scnt[t]);
    if (scnt[t + 256] != 0.f) atomicAdd(&g_cnt[t + 256], scnt[t + 256]);
    for (int o = 128; o; o >>= 1) {
        if (t < o) sh[t] += sh[t + o];
        __syncthreads();
    }
    if (t == 0) g_blocksum[blockIdx.x] = sh[0];
}

// scan3 with scan2 absorbed: every block redundantly scans the 196 block sums
__global__ void scan_part3_kernel() {
    __shared__ int sb[256];
    __shared__ int sh[256];
    int t = threadIdx.x;
    sb[t] = (t < NB) ? g_blocksum[t] : 0;
    __syncthreads();
    for (int o = 1; o < 256; o <<= 1) {
        int v = (t >= o) ? sb[t - o] : 0;
        __syncthreads();
        sb[t] += v;
        __syncthreads();
    }
    int blockoff = (blockIdx.x == 0) ? 0 : sb[blockIdx.x - 1];
    int i = blockIdx.x * 256 + t;
    int v = (i < NN) ? g_deg[i] : 0;
    sh[t] = v;
    __syncthreads();
    for (int o = 1; o < 256; o <<= 1) {
        int u = (t >= o) ? sh[t - o] : 0;
        __syncthreads();
        sh[t] += u;
        __syncthreads();
    }
    if (i < NN) {
        int excl = sh[t] - v + blockoff;
        g_rowptr[i] = excl;
        g_cursor[i] = excl;
        g_invdeg[i] = 1.f / fmaxf((float)v, 1.f);
    }
}

__global__ void place_edges_kernel() {
    for (int i = blockIdx.x * blockDim.x + threadIdx.x; i < EE; i += gridDim.x * blockDim.x) {
        int d = g_dst[i];
        int pos = atomicAdd(&g_cursor[d], 1);
        g_esrc[pos] = g_src[i];
    }
}

// ---------------- gather mean -> g_aggh (fp16): warp per node, MLP 8 ----------------
__global__ __launch_bounds__(256) void gather_kernel() {
    int warp = (blockIdx.x * 256 + threadIdx.x) >> 5;
    if (warp >= NN) return;
    int lane = threadIdx.x & 31;
    int beg = g_rowptr[warp];
    int end = beg + g_deg[warp];

    float4 acc = make_float4(0.f, 0.f, 0.f, 0.f);
    int e = beg;
#pragma unroll 1
    for (; e + 8 <= end; e += 8) {
        int s0 = g_esrc[e + 0];
        int s1 = g_esrc[e + 1];
        int s2 = g_esrc[e + 2];
        int s3 = g_esrc[e + 3];
        int s4 = g_esrc[e + 4];
        int s5 = g_esrc[e + 5];
        int s6 = g_esrc[e + 6];
        int s7 = g_esrc[e + 7];
        uint2 u0 = __ldg((const uint2*)g_xh + (size_t)s0 * 32 + lane);
        uint2 u1 = __ldg((const uint2*)g_xh + (size_t)s1 * 32 + lane);
        uint2 u2 = __ldg((const uint2*)g_xh + (size_t)s2 * 32 + lane);
        uint2 u3 = __ldg((const uint2*)g_xh + (size_t)s3 * 32 + lane);
        uint2 u4 = __ldg((const uint2*)g_xh + (size_t)s4 * 32 + lane);
        uint2 u5 = __ldg((const uint2*)g_xh + (size_t)s5 * 32 + lane);
        uint2 u6 = __ldg((const uint2*)g_xh + (size_t)s6 * 32 + lane);
        uint2 u7 = __ldg((const uint2*)g_xh + (size_t)s7 * 32 + lane);
#pragma unroll
        for (int q = 0; q < 8; q++) {
            uint2 u = (q == 0) ? u0 : (q == 1) ? u1 : (q == 2) ? u2 : (q == 3) ? u3 :
                      (q == 4) ? u4 : (q == 5) ? u5 : (q == 6) ? u6 : u7;
            float2 p0 = __half22float2(*(__half2*)&u.x);
            float2 p1 = __half22float2(*(__half2*)&u.y);
            acc.x += p0.x; acc.y += p0.y; acc.z += p1.x; acc.w += p1.y;
        }
    }
#pragma unroll 1
    for (; e < end; e++) {
        int s = g_esrc[e];
        uint2 u = __ldg((const uint2*)g_xh + (size_t)s * 32 + lane);
        float2 p0 = __half22float2(*(__half2*)&u.x);
        float2 p1 = __half22float2(*(__half2*)&u.y);
        acc.x += p0.x; acc.y += p0.y; acc.z += p1.x; acc.w += p1.y;
    }
    float inv = g_invdeg[warp];
    __half2 h01 = __floats2half2_rn(acc.x * inv, acc.y * inv);
    __half2 h23 = __floats2half2_rn(acc.z * inv, acc.w * inv);
    uint2 st;
    st.x = *(unsigned int*)&h01;
    st.y = *(unsigned int*)&h23;
    *(uint2*)&g_aggh[(size_t)warp * DD + lane * 4] = st;
}

// ---------------- combine via mma.sync fp16: Y = relu([aggh|xh] @ (Wh+Wl)^T + b) ----------------
#define MMAF16(d, a, b0_, b1_) \
    asm volatile("mma.sync.aligned.m16n8k16.row.col.f32.f16.f16.f32 " \
                 "{%0,%1,%2,%3},{%4,%5,%6,%7},{%8,%9},{%0,%1,%2,%3};" \
                 : "+f"(d[0]), "+f"(d[1]), "+f"(d[2]), "+f"(d[3]) \
                 : "r"(a[0]), "r"(a[1]), "r"(a[2]), "r"(a[3]), "r"(b0_), "r"(b1_))

__global__ __launch_bounds__(256, 2) void combine_kernel(
    int layer, const float* __restrict__ bias, const float* __restrict__ fcw, int do_pool)
{
    const __half* __restrict__ Bh = g_Bh + layer * 128 * 256;
    const __half* __restrict__ Bl = g_Bl + layer * 128 * 256;

    __shared__ __half sA[128 * 36];
    __shared__ __half sBh[128 * 36];
    __shared__ __half sBl[128 * 36];
    __shared__ float sdot[128];

    const int tid = threadIdx.x;
    const int lane = tid & 31;
    const int warp = tid >> 5;
    const int wm = warp & 3;
    const int wn = warp >> 2;
    const int row0 = blockIdx.x * 128;
    const int gr = lane >> 2;
    const int tg2 = (lane & 3) * 2;

    if (do_pool && tid < 128) sdot[tid] = 0.f;

    float acc[2][8][4];
#pragma unroll
    for (int mt = 0; mt < 2; mt++)
#pragma unroll
        for (int nt = 0; nt < 8; nt++)
#pragma unroll
            for (int q = 0; q < 4; q++) acc[mt][nt][q] = 0.f;

#pragma unroll 1
    for (int c = 0; c < 8; c++) {
        const int k0 = c * 32;
        const bool from_x = (k0 >= 128);
        const __half* __restrict__ Asrc = from_x ? g_xh : g_aggh;
        const int kb = from_x ? (k0 - 128) : k0;
#pragma unroll
        for (int it = 0; it < 4; it++) {
            int s = tid + it * 256;         // 0..1023
            int r = s >> 3;                 // 0..127
            int c4 = (s & 7) * 4;           // 0..28
            int grow = row0 + r; if (grow >= NN) grow = NN - 1;
            *(uint2*)&sA[r * 36 + c4]  = *(const uint2*)&Asrc[(size_t)grow * DD + kb + c4];
            *(uint2*)&sBh[r * 36 + c4] = *(const uint2*)&Bh[r * 256 + k0 + c4];
            *(uint2*)&sBl[r * 36 + c4] = *(const uint2*)&Bl[r * 256 + k0 + c4];
        }
        __syncthreads();

#pragma unroll
        for (int kk = 0; kk < 32; kk += 16) {
            unsigned int a[2][4];
#pragma unroll
            for (int mt = 0; mt < 2; mt++) {
                int rb = wm * 32 + mt * 16;
                a[mt][0] = *(const unsigned int*)&sA[(rb + gr) * 36 + kk + tg2];
                a[mt][1] = *(const unsigned int*)&sA[(rb + gr + 8) * 36 + kk + tg2];
                a[mt][2] = *(const unsigned int*)&sA[(rb + gr) * 36 + kk + tg2 + 8];
                a[mt][3] = *(const unsigned int*)&sA[(rb + gr + 8) * 36 + kk + tg2 + 8];
            }
#pragma unroll
            for (int nt = 0; nt < 8; nt++) {
                int nb = wn * 64 + nt * 8 + gr;
                unsigned int bh0 = *(const unsigned int*)&sBh[nb * 36 + kk + tg2];
                unsigned int bh1 = *(const unsigned int*)&sBh[nb * 36 + kk + tg2 + 8];
                unsigned int bl0 = *(const unsigned int*)&sBl[nb * 36 + kk + tg2];
                unsigned int bl1 = *(const unsigned int*)&sBl[nb * 36 + kk + tg2 + 8];
#pragma unroll
                for (int mt = 0; mt < 2; mt++) {
                    MMAF16(acc[mt][nt], a[mt], bh0, bh1);
                    MMAF16(acc[mt][nt], a[mt], bl0, bl1);
                }
            }
        }
        __syncthreads();
    }

    // ---- epilogue ----
    if (!do_pool) {
#pragma unroll
        for (int mt = 0; mt < 2; mt++) {
#pragma unroll
            for (int nt = 0; nt < 8; nt++) {
                int col = wn * 64 + nt * 8 + tg2;
                float b0 = bias[col], b1 = bias[col + 1];
#pragma unroll
                for (int half = 0; half < 2; half++) {
                    int row = row0 + wm * 32 + mt * 16 + gr + half * 8;
                    if (row >= NN) continue;
                    float v0 = fmaxf(acc[mt][nt][half * 2 + 0] + b0, 0.f);
                    float v1 = fmaxf(acc[mt][nt][half * 2 + 1] + b1, 0.f);
                    *(__half2*)&g_xh[(size_t)row * DD + col] = __floats2half2_rn(v0, v1);
                }
            }
        }
    } else {
#pragma unroll
        for (int mt = 0; mt < 2; mt++) {
#pragma unroll
            for (int nt = 0; nt < 8; nt++) {
                int col = wn * 64 + nt * 8 + tg2;
                float b0 = bias[col], b1 = bias[col + 1];
                float w0 = fcw[col], w1 = fcw[col + 1];
#pragma unroll
                for (int half = 0; half < 2; half++) {
                    int lr = wm * 32 + mt * 16 + gr + half * 8;
                    float v0 = fmaxf(acc[mt][nt][half * 2 + 0] + b0, 0.f);
                    float v1 = fmaxf(acc[mt][nt][half * 2 + 1] + b1, 0.f);
                    atomicAdd(&sdot[lr], v0 * w0 + v1 * w1);
                }
            }
        }
        __syncthreads();
        if (tid < 128) {
            int grow = row0 + tid;
            if (grow < NN) atomicAdd(&g_acc[g_batch[grow]], sdot[tid]);
        }
    }
}

__global__ void final_kernel(float* __restrict__ out, const float* __restrict__ fcb) {
    int g = blockIdx.x * blockDim.x + threadIdx.x;
    if (g < GG) out[g] = g_acc[g] / fmaxf(g_cnt[g], 1.f) + fcb[0];
}

// ---------------- launch ----------------
extern "C" void kernel_launch(void* const* d_in, const int* in_sizes, int n_in,
                              void* d_out, int out_size) {
    const float* x     = (const float*)d_in[0];
    const void*  ei    = d_in[1];
    const void*  batch = d_in[2];
    const float* Wl[3] = {(const float*)d_in[3], (const float*)d_in[6], (const float*)d_in[9]};
    const float* bb[3] = {(const float*)d_in[4], (const float*)d_in[7], (const float*)d_in[10]};
    const float* Wr[3] = {(const float*)d_in[5], (const float*)d_in[8], (const float*)d_in[11]};
    const float* fcw = (const float*)d_in[12];
    const float* fcb = (const float*)d_in[13];
    float* out = (float*)d_out;

    // prep (5 launches)
    init_kernel<<<NB, 256>>>(ei);
    convert_all_kernel<<<2048, 256>>>(ei, x, Wl[0], Wr[0], Wl[1], Wr[1], Wl[2], Wr[2]);
    scan_part1_kernel<<<NB, 256>>>(batch);
    scan_part3_kernel<<<NB, 256>>>();
    place_edges_kernel<<<4096, 256>>>();

    const int gather_blocks = (NN * 32 + 255) / 256;

    // layer 0: g_xh -> g_aggh -> g_xh (new features)
    gather_kernel<<<gather_blocks, 256>>>();
    combine_kernel<<<CBLK, 256>>>(0, bb[0], fcw, 0);
    // layer 1
    gather_kernel<<<gather_blocks, 256>>>();
    combine_kernel<<<CBLK, 256>>>(1, bb[1], fcw, 0);
    // layer 2: pooled dots (no feature write)
    gather_kernel<<<gather_blocks, 256>>>();
    combine_kernel<<<CBLK, 256>>>(2, bb[2], fcw, 1);

    final_kernel<<<(GG + 255) / 256, 256>>>(out, fcb);
}

// round 12
// speedup vs baseline: 1.4464x; 1.1268x over previous
#include <cuda_runtime.h>
#include <cuda_fp16.h>

#define NN 50000
#define EE 1600000
#define DD 128
#define GG 512
#define NB 196          // ceil(NN/256)
#define CBLK 391        // ceil(NN/128)

// ---------------- scratch (static device globals; no allocation) ----------------
__device__ __half g_aggh[NN * DD];           // fp16 mean-aggregated features
__device__ __half g_xh[NN * DD];             // fp16 current layer features
__device__ __half g_Bh[3 * 128 * 256];       // W fp16
__device__ float g_invdeg[NN];
__device__ int   g_deg[NN];
__device__ int   g_rowptr[NN];
__device__ int   g_cursor[NN];
__device__ int   g_esrc[EE];
__device__ int   g_batch[NN];
__device__ float g_acc[GG];
__device__ float g_cnt[GG];
__device__ int   g_blocksum[NB];
__device__ int   g_is64;

// ---------------- init: zero scratch + dtype probe (one launch) ----------------
__global__ void init_kernel(const void* __restrict__ ei) {
    int i = blockIdx.x * blockDim.x + threadIdx.x;
    if (i < NN) g_deg[i] = 0;
    if (i < GG) { g_acc[i] = 0.f; g_cnt[i] = 0.f; }
    if (i == 0) {
        const long long* p = (const long long*)ei;
        int ok = 1;
#pragma unroll 1
        for (int j = 0; j < 64; j++) {
            long long v = p[j];
            if (v < 0 || v >= NN) ok = 0;
        }
        g_is64 = ok;
    }
}

// ---------------- convert_all: deg histogram (direct from ei), x->fp16, weights->fp16 ----------------
__global__ void convert_all_kernel(const void* __restrict__ ei, const float* __restrict__ x,
                                   const float* __restrict__ Wl0, const float* __restrict__ Wr0,
                                   const float* __restrict__ Wl1, const float* __restrict__ Wr1,
                                   const float* __restrict__ Wl2, const float* __restrict__ Wr2) {
    const int gs = gridDim.x * blockDim.x;
    const int t0 = blockIdx.x * blockDim.x + threadIdx.x;
    const int is64 = g_is64;
    const long long* p64 = (const long long*)ei;
    const int*       p32 = (const int*)ei;
    // 1. degree histogram (dst half of edge_index only)
    for (int i = t0; i < EE; i += gs) {
        int d = is64 ? (int)p64[EE + i] : p32[EE + i];
        atomicAdd(&g_deg[d], 1);
    }
    // 2. x -> fp16
    for (int i = t0; i < NN * DD / 2; i += gs) {
        float2 v = ((const float2*)x)[i];
        ((__half2*)g_xh)[i] = __floats2half2_rn(v.x, v.y);
    }
    // 3. weights -> fp16
    for (int i = t0; i < 3 * 128 * 256; i += gs) {
        int l = i >> 15;
        int j = i & 32767;
        int n = j >> 8, k = j & 255;
        const float* Wl = (l == 0) ? Wl0 : (l == 1 ? Wl1 : Wl2);
        const float* Wr = (l == 0) ? Wr0 : (l == 1 ? Wr1 : Wr2);
        float v = (k < 128) ? Wl[n * 128 + k] : Wr[n * 128 + (k - 128)];
        g_Bh[i] = __float2half_rn(v);
    }
}

// ---------------- scan for CSR (+batch conversion folded into part1) ----------------
__global__ void scan_part1_kernel(const void* __restrict__ b) {
    __shared__ int sh[256];
    __shared__ float scnt[GG];
    const int t = threadIdx.x;
    const int i = blockIdx.x * 256 + t;
    int v = (i < NN) ? g_deg[i] : 0;
    sh[t] = v;
    scnt[t] = 0.f; scnt[t + 256] = 0.f;
    __syncthreads();
    if (i < NN) {
        const int is64 = g_is64;
        int g = is64 ? (int)((const long long*)b)[i] : ((const int*)b)[i];
        g_batch[i] = g;
        atomicAdd(&scnt[g], 1.f);
    }
    __syncthreads();
    if (scnt[t] != 0.f) atomicAdd(&g_cnt[t], scnt[t]);
    if (scnt[t + 256] != 0.f) atomicAdd(&g_cnt[t + 256], scnt[t + 256]);
    for (int o = 128; o; o >>= 1) {
        if (t < o) sh[t] += sh[t + o];
        __syncthreads();
    }
    if (t == 0) g_blocksum[blockIdx.x] = sh[0];
}

// scan3 with scan2 absorbed: every block redundantly scans the 196 block sums
__global__ void scan_part3_kernel() {
    __shared__ int sb[256];
    __shared__ int sh[256];
    int t = threadIdx.x;
    sb[t] = (t < NB) ? g_blocksum[t] : 0;
    __syncthreads();
    for (int o = 1; o < 256; o <<= 1) {
        int v = (t >= o) ? sb[t - o] : 0;
        __syncthreads();
        sb[t] += v;
        __syncthreads();
    }
    int blockoff = (blockIdx.x == 0) ? 0 : sb[blockIdx.x - 1];
    int i = blockIdx.x * 256 + t;
    int v = (i < NN) ? g_deg[i] : 0;
    sh[t] = v;
    __syncthreads();
    for (int o = 1; o < 256; o <<= 1) {
        int u = (t >= o) ? sh[t - o] : 0;
        __syncthreads();
        sh[t] += u;
        __syncthreads();
    }
    if (i < NN) {
        int excl = sh[t] - v + blockoff;
        g_rowptr[i] = excl;
        g_cursor[i] = excl;
        g_invdeg[i] = 1.f / fmaxf((float)v, 1.f);
    }
}

// place edges directly from ei (no staging buffers)
__global__ void place_edges_kernel(const void* __restrict__ ei) {
    const int is64 = g_is64;
    const long long* p64 = (const long long*)ei;
    const int*       p32 = (const int*)ei;
    for (int i = blockIdx.x * blockDim.x + threadIdx.x; i < EE; i += gridDim.x * blockDim.x) {
        int s, d;
        if (is64) { s = (int)p64[i]; d = (int)p64[EE + i]; }
        else      { s = p32[i];      d = p32[EE + i]; }
        int pos = atomicAdd(&g_cursor[d], 1);
        g_esrc[pos] = s;
    }
}

// ---------------- gather mean -> g_aggh (fp16): warp per node, MLP 8, int4 index loads ----------------
__global__ __launch_bounds__(256) void gather_kernel() {
    int warp = (blockIdx.x * 256 + threadIdx.x) >> 5;
    if (warp >= NN) return;
    int lane = threadIdx.x & 31;
    int beg = g_rowptr[warp];
    int end = beg + g_deg[warp];

    float4 acc = make_float4(0.f, 0.f, 0.f, 0.f);
    int e = beg;
    // peel to 4-edge alignment so int4 index loads are 16B-aligned
    int pre = (4 - (beg & 3)) & 3;
    if (pre > end - beg) pre = end - beg;
#pragma unroll 1
    for (int q = 0; q < pre; q++, e++) {
        int s = g_esrc[e];
        uint2 u = __ldg((const uint2*)g_xh + (size_t)s * 32 + lane);
        float2 p0 = __half22float2(*(__half2*)&u.x);
        float2 p1 = __half22float2(*(__half2*)&u.y);
        acc.x += p0.x; acc.y += p0.y; acc.z += p1.x; acc.w += p1.y;
    }
#pragma unroll 1
    for (; e + 8 <= end; e += 8) {
        int4 ia = *(const int4*)(g_esrc + e);
        int4 ib = *(const int4*)(g_esrc + e + 4);
        uint2 u0 = __ldg((const uint2*)g_xh + (size_t)ia.x * 32 + lane);
        uint2 u1 = __ldg((const uint2*)g_xh + (size_t)ia.y * 32 + lane);
        uint2 u2 = __ldg((const uint2*)g_xh + (size_t)ia.z * 32 + lane);
        uint2 u3 = __ldg((const uint2*)g_xh + (size_t)ia.w * 32 + lane);
        uint2 u4 = __ldg((const uint2*)g_xh + (size_t)ib.x * 32 + lane);
        uint2 u5 = __ldg((const uint2*)g_xh + (size_t)ib.y * 32 + lane);
        uint2 u6 = __ldg((const uint2*)g_xh + (size_t)ib.z * 32 + lane);
        uint2 u7 = __ldg((const uint2*)g_xh + (size_t)ib.w * 32 + lane);
#pragma unroll
        for (int q = 0; q < 8; q++) {
            uint2 u = (q == 0) ? u0 : (q == 1) ? u1 : (q == 2) ? u2 : (q == 3) ? u3 :
                      (q == 4) ? u4 : (q == 5) ? u5 : (q == 6) ? u6 : u7;
            float2 p0 = __half22float2(*(__half2*)&u.x);
            float2 p1 = __half22float2(*(__half2*)&u.y);
            acc.x += p0.x; acc.y += p0.y; acc.z += p1.x; acc.w += p1.y;
        }
    }
#pragma unroll 1
    for (; e < end; e++) {
        int s = g_esrc[e];
        uint2 u = __ldg((const uint2*)g_xh + (size_t)s * 32 + lane);
        float2 p0 = __half22float2(*(__half2*)&u.x);
        float2 p1 = __half22float2(*(__half2*)&u.y);
        acc.x += p0.x; acc.y += p0.y; acc.z += p1.x; acc.w += p1.y;
    }
    float inv = g_invdeg[warp];
    __half2 h01 = __floats2half2_rn(acc.x * inv, acc.y * inv);
    __half2 h23 = __floats2half2_rn(acc.z * inv, acc.w * inv);
    uint2 st;
    st.x = *(unsigned int*)&h01;
    st.y = *(unsigned int*)&h23;
    *(uint2*)&g_aggh[(size_t)warp * DD + lane * 4] = st;
}

// ---------------- combine via single fp16 mma.sync: Y = relu([aggh|xh] @ W^T + b) ----------------
#define MMAF16(d, a, b0_, b1_) \
    asm volatile("mma.sync.aligned.m16n8k16.row.col.f32.f16.f16.f32 " \
                 "{%0,%1,%2,%3},{%4,%5,%6,%7},{%8,%9},{%0,%1,%2,%3};" \
                 : "+f"(d[0]), "+f"(d[1]), "+f"(d[2]), "+f"(d[3]) \
                 : "r"(a[0]), "r"(a[1]), "r"(a[2]), "r"(a[3]), "r"(b0_), "r"(b1_))

__global__ __launch_bounds__(256, 2) void combine_kernel(
    int layer, const float* __restrict__ bias, const float* __restrict__ fcw, int do_pool)
{
    const __half* __restrict__ Bh = g_Bh + layer * 128 * 256;

    __shared__ __half sA[128 * 36];
    __shared__ __half sB[128 * 36];
    __shared__ float sdot[128];

    const int tid = threadIdx.x;
    const int lane = tid & 31;
    const int warp = tid >> 5;
    const int wm = warp & 3;
    const int wn = warp >> 2;
    const int row0 = blockIdx.x * 128;
    const int gr = lane >> 2;
    const int tg2 = (lane & 3) * 2;

    if (do_pool && tid < 128) sdot[tid] = 0.f;

    float acc[2][8][4];
#pragma unroll
    for (int mt = 0; mt < 2; mt++)
#pragma unroll
        for (int nt = 0; nt < 8; nt++)
#pragma unroll
            for (int q = 0; q < 4; q++) acc[mt][nt][q] = 0.f;

#pragma unroll 1
    for (int c = 0; c < 8; c++) {
        const int k0 = c * 32;
        const bool from_x = (k0 >= 128);
        const __half* __restrict__ Asrc = from_x ? g_xh : g_aggh;
        const int kb = from_x ? (k0 - 128) : k0;
#pragma unroll
        for (int it = 0; it < 4; it++) {
            int s = tid + it * 256;         // 0..1023
            int r = s >> 3;                 // 0..127
            int c4 = (s & 7) * 4;           // 0..28
            int grow = row0 + r; if (grow >= NN) grow = NN - 1;
            *(uint2*)&sA[r * 36 + c4] = *(const uint2*)&Asrc[(size_t)grow * DD + kb + c4];
            *(uint2*)&sB[r * 36 + c4] = *(const uint2*)&Bh[r * 256 + k0 + c4];
        }
        __syncthreads();

#pragma unroll
        for (int kk = 0; kk < 32; kk += 16) {
            unsigned int a[2][4];
#pragma unroll
            for (int mt = 0; mt < 2; mt++) {
                int rb = wm * 32 + mt * 16;
                a[mt][0] = *(const unsigned int*)&sA[(rb + gr) * 36 + kk + tg2];
                a[mt][1] = *(const unsigned int*)&sA[(rb + gr + 8) * 36 + kk + tg2];
                a[mt][2] = *(const unsigned int*)&sA[(rb + gr) * 36 + kk + tg2 + 8];
                a[mt][3] = *(const unsigned int*)&sA[(rb + gr + 8) * 36 + kk + tg2 + 8];
            }
#pragma unroll
            for (int nt = 0; nt < 8; nt++) {
                int nb = wn * 64 + nt * 8 + gr;
                unsigned int b0 = *(const unsigned int*)&sB[nb * 36 + kk + tg2];
                unsigned int b1 = *(const unsigned int*)&sB[nb * 36 + kk + tg2 + 8];
#pragma unroll
                for (int mt = 0; mt < 2; mt++) {
                    MMAF16(acc[mt][nt], a[mt], b0, b1);
                }
            }
        }
        __syncthreads();
    }

    // ---- epilogue ----
    if (!do_pool) {
#pragma unroll
        for (int mt = 0; mt < 2; mt++) {
#pragma unroll
            for (int nt = 0; nt < 8; nt++) {
                int col = wn * 64 + nt * 8 + tg2;
                float b0 = bias[col], b1 = bias[col + 1];
#pragma unroll
                for (int half = 0; half < 2; half++) {
                    int row = row0 + wm * 32 + mt * 16 + gr + half * 8;
                    if (row >= NN) continue;
                    float v0 = fmaxf(acc[mt][nt][half * 2 + 0] + b0, 0.f);
                    float v1 = fmaxf(acc[mt][nt][half * 2 + 1] + b1, 0.f);
                    *(__half2*)&g_xh[(size_t)row * DD + col] = __floats2half2_rn(v0, v1);
                }
            }
        }
    } else {
#pragma unroll
        for (int mt = 0; mt < 2; mt++) {
#pragma unroll
            for (int nt = 0; nt < 8; nt++) {
                int col = wn * 64 + nt * 8 + tg2;
                float b0 = bias[col], b1 = bias[col + 1];
                float w0 = fcw[col], w1 = fcw[col + 1];
#pragma unroll
                for (int half = 0; half < 2; half++) {
                    int lr = wm * 32 + mt * 16 + gr + half * 8;
                    float v0 = fmaxf(acc[mt][nt][half * 2 + 0] + b0, 0.f);
                    float v1 = fmaxf(acc[mt][nt][half * 2 + 1] + b1, 0.f);
                    atomicAdd(&sdot[lr], v0 * w0 + v1 * w1);
                }
            }
        }
        __syncthreads();
        if (tid < 128) {
            int grow = row0 + tid;
            if (grow < NN) atomicAdd(&g_acc[g_batch[grow]], sdot[tid]);
        }
    }
}

__global__ void final_kernel(float* __restrict__ out, const float* __restrict__ fcb) {
    int g = blockIdx.x * blockDim.x + threadIdx.x;
    if (g < GG) out[g] = g_acc[g] / fmaxf(g_cnt[g], 1.f) + fcb[0];
}

// ---------------- launch ----------------
extern "C" void kernel_launch(void* const* d_in, const int* in_sizes, int n_in,
                              void* d_out, int out_size) {
    const float* x     = (const float*)d_in[0];
    const void*  ei    = d_in[1];
    const void*  batch = d_in[2];
    const float* Wl[3] = {(const float*)d_in[3], (const float*)d_in[6], (const float*)d_in[9]};
    const float* bb[3] = {(const float*)d_in[4], (const float*)d_in[7], (const float*)d_in[10]};
    const float* Wr[3] = {(const float*)d_in[5], (const float*)d_in[8], (const float*)d_in[11]};
    const float* fcw = (const float*)d_in[12];
    const float* fcb = (const float*)d_in[13];
    float* out = (float*)d_out;

    // prep (5 launches)
    init_kernel<<<NB, 256>>>(ei);
    convert_all_kernel<<<2048, 256>>>(ei, x, Wl[0], Wr[0], Wl[1], Wr[1], Wl[2], Wr[2]);
    scan_part1_kernel<<<NB, 256>>>(batch);
    scan_part3_kernel<<<NB, 256>>>();
    place_edges_kernel<<<4096, 256>>>(ei);

    const int gather_blocks = (NN * 32 + 255) / 256;

    // layer 0: g_xh -> g_aggh -> g_xh (new features)
    gather_kernel<<<gather_blocks, 256>>>();
    combine_kernel<<<CBLK, 256>>>(0, bb[0], fcw, 0);
    // layer 1
    gather_kernel<<<gather_blocks, 256>>>();
    combine_kernel<<<CBLK, 256>>>(1, bb[1], fcw, 0);
    // layer 2: pooled dots (no feature write)
    gather_kernel<<<gather_blocks, 256>>>();
    combine_kernel<<<CBLK, 256>>>(2, bb[2], fcw, 1);

    final_kernel<<<(GG + 255) / 256, 256>>>(out, fcb);
}

// round 13
// speedup vs baseline: 1.4653x; 1.0131x over previous
#include <cuda_runtime.h>
#include <cuda_fp16.h>

#define NN 50000
#define EE 1600000
#define DD 128
#define GG 512
#define NB 196          // ceil(NN/256)
#define CBLK 391        // ceil(NN/128)

// ---------------- scratch (static device globals; no allocation) ----------------
__device__ __half g_aggh[NN * DD];           // fp16 mean-aggregated features
__device__ __half g_xh[NN * DD];             // fp16 current layer features
__device__ __half g_Bh[3 * 128 * 256];       // W fp16
__device__ float g_invdeg[NN];
__device__ int   g_deg[NN];
__device__ int   g_rowptr[NN];
__device__ int   g_cursor[NN];
__device__ int   g_esrc[EE];
__device__ int   g_batch[NN];
__device__ float g_acc[GG];
__device__ float g_cnt[GG];
__device__ int   g_blocksum[NB];
__device__ int   g_is64;

// ---------------- init: zero scratch + dtype probe (one launch) ----------------
__global__ void init_kernel(const void* __restrict__ ei) {
    int i = blockIdx.x * blockDim.x + threadIdx.x;
    if (i < NN) g_deg[i] = 0;
    if (i < GG) { g_acc[i] = 0.f; g_cnt[i] = 0.f; }
    if (i == 0) {
        const long long* p = (const long long*)ei;
        int ok = 1;
#pragma unroll 1
        for (int j = 0; j < 64; j++) {
            long long v = p[j];
            if (v < 0 || v >= NN) ok = 0;
        }
        g_is64 = ok;
    }
}

// ---------------- convert_all: deg histogram (direct from ei), x->fp16, weights->fp16 ----------------
__global__ void convert_all_kernel(const void* __restrict__ ei, const float* __restrict__ x,
                                   const float* __restrict__ Wl0, const float* __restrict__ Wr0,
                                   const float* __restrict__ Wl1, const float* __restrict__ Wr1,
                                   const float* __restrict__ Wl2, const float* __restrict__ Wr2) {
    const int gs = gridDim.x * blockDim.x;
    const int t0 = blockIdx.x * blockDim.x + threadIdx.x;
    const int is64 = g_is64;
    const long long* p64 = (const long long*)ei;
    const int*       p32 = (const int*)ei;
    // 1. degree histogram (dst half of edge_index only)
    for (int i = t0; i < EE; i += gs) {
        int d = is64 ? (int)p64[EE + i] : p32[EE + i];
        atomicAdd(&g_deg[d], 1);
    }
    // 2. x -> fp16
    for (int i = t0; i < NN * DD / 2; i += gs) {
        float2 v = ((const float2*)x)[i];
        ((__half2*)g_xh)[i] = __floats2half2_rn(v.x, v.y);
    }
    // 3. weights -> fp16
    for (int i = t0; i < 3 * 128 * 256; i += gs) {
        int l = i >> 15;
        int j = i & 32767;
        int n = j >> 8, k = j & 255;
        const float* Wl = (l == 0) ? Wl0 : (l == 1 ? Wl1 : Wl2);
        const float* Wr = (l == 0) ? Wr0 : (l == 1 ? Wr1 : Wr2);
        float v = (k < 128) ? Wl[n * 128 + k] : Wr[n * 128 + (k - 128)];
        g_Bh[i] = __float2half_rn(v);
    }
}

// ---------------- scan for CSR (+batch conversion folded into part1) ----------------
__global__ void scan_part1_kernel(const void* __restrict__ b) {
    __shared__ int sh[256];
    __shared__ float scnt[GG];
    const int t = threadIdx.x;
    const int i = blockIdx.x * 256 + t;
    int v = (i < NN) ? g_deg[i] : 0;
    sh[t] = v;
    scnt[t] = 0.f; scnt[t + 256] = 0.f;
    __syncthreads();
    if (i < NN) {
        const int is64 = g_is64;
        int g = is64 ? (int)((const long long*)b)[i] : ((const int*)b)[i];
        g_batch[i] = g;
        atomicAdd(&scnt[g], 1.f);
    }
    __syncthreads();
    if (scnt[t] != 0.f) atomicAdd(&g_cnt[t], scnt[t]);
    if (scnt[t + 256] != 0.f) atomicAdd(&g_cnt[t + 256], scnt[t + 256]);
    for (int o = 128; o; o >>= 1) {
        if (t < o) sh[t] += sh[t + o];
        __syncthreads();
    }
    if (t == 0) g_blocksum[blockIdx.x] = sh[0];
}

// scan3 with scan2 absorbed: every block redundantly scans the 196 block sums
__global__ void scan_part3_kernel() {
    __shared__ int sb[256];
    __shared__ int sh[256];
    int t = threadIdx.x;
    sb[t] = (t < NB) ? g_blocksum[t] : 0;
    __syncthreads();
    for (int o = 1; o < 256; o <<= 1) {
        int v = (t >= o) ? sb[t - o] : 0;
        __syncthreads();
        sb[t] += v;
        __syncthreads();
    }
    int blockoff = (blockIdx.x == 0) ? 0 : sb[blockIdx.x - 1];
    int i = blockIdx.x * 256 + t;
    int v = (i < NN) ? g_deg[i] : 0;
    sh[t] = v;
    __syncthreads();
    for (int o = 1; o < 256; o <<= 1) {
        int u = (t >= o) ? sh[t - o] : 0;
        __syncthreads();
        sh[t] += u;
        __syncthreads();
    }
    if (i < NN) {
        int excl = sh[t] - v + blockoff;
        g_rowptr[i] = excl;
        g_cursor[i] = excl;
        g_invdeg[i] = 1.f / fmaxf((float)v, 1.f);
    }
}

// place edges directly from ei (no staging buffers)
__global__ void place_edges_kernel(const void* __restrict__ ei) {
    const int is64 = g_is64;
    const long long* p64 = (const long long*)ei;
    const int*       p32 = (const int*)ei;
    for (int i = blockIdx.x * blockDim.x + threadIdx.x; i < EE; i += gridDim.x * blockDim.x) {
        int s, d;
        if (is64) { s = (int)p64[i]; d = (int)p64[EE + i]; }
        else      { s = p32[i];      d = p32[EE + i]; }
        int pos = atomicAdd(&g_cursor[d], 1);
        g_esrc[pos] = s;
    }
}

// ---------------- gather mean -> g_aggh: 2 edges per LDG.128, register-broadcast indices ----------------
// warp per node; lanes 0-15 = even edge of pair, lanes 16-31 = odd edge.
// lane (h, sub) accumulates columns sub*8 .. sub*8+7; final shfl_xor(16) merges halves.
__global__ __launch_bounds__(256) void gather_kernel() {
    const unsigned FULL = 0xffffffffu;
    int node = (blockIdx.x * 256 + threadIdx.x) >> 5;
    if (node >= NN) return;
    const int lane = threadIdx.x & 31;
    const int hw = lane >> 4;         // which edge of the pair
    const int sub = lane & 15;        // 16B chunk within 256B row
    const int beg = g_rowptr[node];
    const int end = beg + g_deg[node];

    float a0 = 0.f, a1 = 0.f, a2 = 0.f, a3 = 0.f, a4 = 0.f, a5 = 0.f, a6 = 0.f, a7 = 0.f;
    int e = beg;

#define ACC_ROW(vv) do { \
        float2 p; \
        p = __half22float2(*(__half2*)&(vv).x); a0 += p.x; a1 += p.y; \
        p = __half22float2(*(__half2*)&(vv).y); a2 += p.x; a3 += p.y; \
        p = __half22float2(*(__half2*)&(vv).z); a4 += p.x; a5 += p.y; \
        p = __half22float2(*(__half2*)&(vv).w); a6 += p.x; a7 += p.y; \
    } while (0)

    // peel to 4-edge alignment (single edges, half-warp covers the row)
    int pre = (4 - (beg & 3)) & 3;
    if (pre > end - beg) pre = end - beg;
#pragma unroll 1
    for (int q = 0; q < pre; q++, e++) {
        int s = g_esrc[e];
        if (hw == 0) {
            uint4 v = __ldg((const uint4*)g_xh + (size_t)s * 16 + sub);
            ACC_ROW(v);
        }
    }

    // main: 8 edges per iteration, 2 int4 index loads + 4 LDG.128 payloads per lane
#pragma unroll 1
    for (; e + 8 <= end; e += 8) {
        int4 ia = *(const int4*)(g_esrc + e);
        int4 ib = *(const int4*)(g_esrc + e + 4);
        int s0 = hw ? ia.y : ia.x;
        int s1 = hw ? ia.w : ia.z;
        int s2 = hw ? ib.y : ib.x;
        int s3 = hw ? ib.w : ib.z;
        uint4 v0 = __ldg((const uint4*)g_xh + (size_t)s0 * 16 + sub);
        uint4 v1 = __ldg((const uint4*)g_xh + (size_t)s1 * 16 + sub);
        uint4 v2 = __ldg((const uint4*)g_xh + (size_t)s2 * 16 + sub);
        uint4 v3 = __ldg((const uint4*)g_xh + (size_t)s3 * 16 + sub);
        ACC_ROW(v0); ACC_ROW(v1); ACC_ROW(v2); ACC_ROW(v3);
    }

    // tail pairs
#pragma unroll 1
    for (; e + 2 <= end; e += 2) {
        int sa = g_esrc[e], sbb = g_esrc[e + 1];
        int s = hw ? sbb : sa;
        uint4 v = __ldg((const uint4*)g_xh + (size_t)s * 16 + sub);
        ACC_ROW(v);
    }
    // single leftover
    if (e < end) {
        int s = g_esrc[e];
        if (hw == 0) {
            uint4 v = __ldg((const uint4*)g_xh + (size_t)s * 16 + sub);
            ACC_ROW(v);
        }
    }
#undef ACC_ROW

    // merge the two half-warp partial sums
    a0 += __shfl_xor_sync(FULL, a0, 16);
    a1 += __shfl_xor_sync(FULL, a1, 16);
    a2 += __shfl_xor_sync(FULL, a2, 16);
    a3 += __shfl_xor_sync(FULL, a3, 16);
    a4 += __shfl_xor_sync(FULL, a4, 16);
    a5 += __shfl_xor_sync(FULL, a5, 16);
    a6 += __shfl_xor_sync(FULL, a6, 16);
    a7 += __shfl_xor_sync(FULL, a7, 16);

    if (hw == 0) {
        float inv = g_invdeg[node];
        __half2 h0 = __floats2half2_rn(a0 * inv, a1 * inv);
        __half2 h1 = __floats2half2_rn(a2 * inv, a3 * inv);
        __half2 h2 = __floats2half2_rn(a4 * inv, a5 * inv);
        __half2 h3 = __floats2half2_rn(a6 * inv, a7 * inv);
        uint4 st;
        st.x = *(unsigned int*)&h0;
        st.y = *(unsigned int*)&h1;
        st.z = *(unsigned int*)&h2;
        st.w = *(unsigned int*)&h3;
        *((uint4*)g_aggh + (size_t)node * 16 + sub) = st;
    }
}

// ---------------- combine via single fp16 mma.sync: Y = relu([aggh|xh] @ W^T + b) ----------------
#define MMAF16(d, a, b0_, b1_) \
    asm volatile("mma.sync.aligned.m16n8k16.row.col.f32.f16.f16.f32 " \
                 "{%0,%1,%2,%3},{%4,%5,%6,%7},{%8,%9},{%0,%1,%2,%3};" \
                 : "+f"(d[0]), "+f"(d[1]), "+f"(d[2]), "+f"(d[3]) \
                 : "r"(a[0]), "r"(a[1]), "r"(a[2]), "r"(a[3]), "r"(b0_), "r"(b1_))

__global__ __launch_bounds__(256, 2) void combine_kernel(
    int layer, const float* __restrict__ bias, const float* __restrict__ fcw, int do_pool)
{
    const __half* __restrict__ Bh = g_Bh + layer * 128 * 256;

    __shared__ __half sA[128 * 36];
    __shared__ __half sB[128 * 36];
    __shared__ float sdot[128];

    const int tid = threadIdx.x;
    const int lane = tid & 31;
    const int warp = tid >> 5;
    const int wm = warp & 3;
    const int wn = warp >> 2;
    const int row0 = blockIdx.x * 128;
    const int gr = lane >> 2;
    const int tg2 = (lane & 3) * 2;

    if (do_pool && tid < 128) sdot[tid] = 0.f;

    float acc[2][8][4];
#pragma unroll
    for (int mt = 0; mt < 2; mt++)
#pragma unroll
        for (int nt = 0; nt < 8; nt++)
#pragma unroll
            for (int q = 0; q < 4; q++) acc[mt][nt][q] = 0.f;

#pragma unroll 1
    for (int c = 0; c < 8; c++) {
        const int k0 = c * 32;
        const bool from_x = (k0 >= 128);
        const __half* __restrict__ Asrc = from_x ? g_xh : g_aggh;
        const int kb = from_x ? (k0 - 128) : k0;
#pragma unroll
        for (int it = 0; it < 4; it++) {
            int s = tid + it * 256;         // 0..1023
            int r = s >> 3;                 // 0..127
            int c4 = (s & 7) * 4;           // 0..28
            int grow = row0 + r; if (grow >= NN) grow = NN - 1;
            *(uint2*)&sA[r * 36 + c4] = *(const uint2*)&Asrc[(size_t)grow * DD + kb + c4];
            *(uint2*)&sB[r * 36 + c4] = *(const uint2*)&Bh[r * 256 + k0 + c4];
        }
        __syncthreads();

#pragma unroll
        for (int kk = 0; kk < 32; kk += 16) {
            unsigned int a[2][4];
#pragma unroll
            for (int mt = 0; mt < 2; mt++) {
                int rb = wm * 32 + mt * 16;
                a[mt][0] = *(const unsigned int*)&sA[(rb + gr) * 36 + kk + tg2];
                a[mt][1] = *(const unsigned int*)&sA[(rb + gr + 8) * 36 + kk + tg2];
                a[mt][2] = *(const unsigned int*)&sA[(rb + gr) * 36 + kk + tg2 + 8];
                a[mt][3] = *(const unsigned int*)&sA[(rb + gr + 8) * 36 + kk + tg2 + 8];
            }
#pragma unroll
            for (int nt = 0; nt < 8; nt++) {
                int nb = wn * 64 + nt * 8 + gr;
                unsigned int b0 = *(const unsigned int*)&sB[nb * 36 + kk + tg2];
                unsigned int b1 = *(const unsigned int*)&sB[nb * 36 + kk + tg2 + 8];
#pragma unroll
                for (int mt = 0; mt < 2; mt++) {
                    MMAF16(acc[mt][nt], a[mt], b0, b1);
                }
            }
        }
        __syncthreads();
    }

    // ---- epilogue ----
    if (!do_pool) {
#pragma unroll
        for (int mt = 0; mt < 2; mt++) {
#pragma unroll
            for (int nt = 0; nt < 8; nt++) {
                int col = wn * 64 + nt * 8 + tg2;
                float b0 = bias[col], b1 = bias[col + 1];
#pragma unroll
                for (int half = 0; half < 2; half++) {
                    int row = row0 + wm * 32 + mt * 16 + gr + half * 8;
                    if (row >= NN) continue;
                    float v0 = fmaxf(acc[mt][nt][half * 2 + 0] + b0, 0.f);
                    float v1 = fmaxf(acc[mt][nt][half * 2 + 1] + b1, 0.f);
                    *(__half2*)&g_xh[(size_t)row * DD + col] = __floats2half2_rn(v0, v1);
                }
            }
        }
    } else {
#pragma unroll
        for (int mt = 0; mt < 2; mt++) {
#pragma unroll
            for (int nt = 0; nt < 8; nt++) {
                int col = wn * 64 + nt * 8 + tg2;
                float b0 = bias[col], b1 = bias[col + 1];
                float w0 = fcw[col], w1 = fcw[col + 1];
#pragma unroll
                for (int half = 0; half < 2; half++) {
                    int lr = wm * 32 + mt * 16 + gr + half * 8;
                    float v0 = fmaxf(acc[mt][nt][half * 2 + 0] + b0, 0.f);
                    float v1 = fmaxf(acc[mt][nt][half * 2 + 1] + b1, 0.f);
                    atomicAdd(&sdot[lr], v0 * w0 + v1 * w1);
                }
            }
        }
        __syncthreads();
        if (tid < 128) {
            int grow = row0 + tid;
            if (grow < NN) atomicAdd(&g_acc[g_batch[grow]], sdot[tid]);
        }
    }
}

__global__ void final_kernel(float* __restrict__ out, const float* __restrict__ fcb) {
    int g = blockIdx.x * blockDim.x + threadIdx.x;
    if (g < GG) out[g] = g_acc[g] / fmaxf(g_cnt[g], 1.f) + fcb[0];
}

// ---------------- launch ----------------
extern "C" void kernel_launch(void* const* d_in, const int* in_sizes, int n_in,
                              void* d_out, int out_size) {
    const float* x     = (const float*)d_in[0];
    const void*  ei    = d_in[1];
    const void*  batch = d_in[2];
    const float* Wl[3] = {(const float*)d_in[3], (const float*)d_in[6], (const float*)d_in[9]};
    const float* bb[3] = {(const float*)d_in[4], (const float*)d_in[7], (const float*)d_in[10]};
    const float* Wr[3] = {(const float*)d_in[5], (const float*)d_in[8], (const float*)d_in[11]};
    const float* fcw = (const float*)d_in[12];
    const float* fcb = (const float*)d_in[13];
    float* out = (float*)d_out;

    // prep (5 launches)
    init_kernel<<<NB, 256>>>(ei);
    convert_all_kernel<<<2048, 256>>>(ei, x, Wl[0], Wr[0], Wl[1], Wr[1], Wl[2], Wr[2]);
    scan_part1_kernel<<<NB, 256>>>(batch);
    scan_part3_kernel<<<NB, 256>>>();
    place_edges_kernel<<<4096, 256>>>(ei);

    const int gather_blocks = (NN * 32 + 255) / 256;

    // layer 0: g_xh -> g_aggh -> g_xh (new features)
    gather_kernel<<<gather_blocks, 256>>>();
    combine_kernel<<<CBLK, 256>>>(0, bb[0], fcw, 0);
    // layer 1
    gather_kernel<<<gather_blocks, 256>>>();
    combine_kernel<<<CBLK, 256>>>(1, bb[1], fcw, 0);
    // layer 2: pooled dots (no feature write)
    gather_kernel<<<gather_blocks, 256>>>();
    combine_kernel<<<CBLK, 256>>>(2, bb[2], fcw, 1);

    final_kernel<<<(GG + 255) / 256, 256>>>(out, fcb);
}

// round 14
// speedup vs baseline: 1.4888x; 1.0161x over previous
#include <cuda_runtime.h>
#include <cuda_fp16.h>

#define NN 50000
#define EE 1600000
#define DD 128
#define GG 512
#define NB 196          // ceil(NN/256)
#define CBLK 391        // ceil(NN/128)

// ---------------- scratch (static device globals; no allocation) ----------------
__device__ __half g_aggh[NN * DD];           // fp16 mean-aggregated features
__device__ __half g_xh[NN * DD];             // fp16 current layer features
__device__ __half g_Bh[3 * 128 * 256];       // W fp16
__device__ float g_invdeg[NN];
__device__ int   g_deg[NN];
__device__ int   g_rowptr[NN];
__device__ int   g_cursor[NN];
__device__ int   g_esrc[EE];
__device__ int   g_batch[NN];
__device__ float g_acc[GG];
__device__ float g_cnt[GG];
__device__ int   g_blocksum[NB];
__device__ int   g_is64;

// ---------------- init: zero scratch + dtype probe (one launch) ----------------
__global__ void init_kernel(const void* __restrict__ ei) {
    int i = blockIdx.x * blockDim.x + threadIdx.x;
    if (i < NN) g_deg[i] = 0;
    if (i < GG) { g_acc[i] = 0.f; g_cnt[i] = 0.f; }
    if (i == 0) {
        const long long* p = (const long long*)ei;
        int ok = 1;
#pragma unroll 1
        for (int j = 0; j < 64; j++) {
            long long v = p[j];
            if (v < 0 || v >= NN) ok = 0;
        }
        g_is64 = ok;
    }
}

// ---------------- deg histogram (critical path) ----------------
__global__ void deg_hist_kernel(const void* __restrict__ ei) {
    const int is64 = g_is64;
    const long long* p64 = (const long long*)ei;
    const int*       p32 = (const int*)ei;
    for (int i = blockIdx.x * blockDim.x + threadIdx.x; i < EE; i += gridDim.x * blockDim.x) {
        int d = is64 ? (int)p64[EE + i] : p32[EE + i];
        atomicAdd(&g_deg[d], 1);
    }
}

// ---------------- side stream: x->fp16 + weights->fp16 ----------------
__global__ void convert_xw_kernel(const float* __restrict__ x,
                                  const float* __restrict__ Wl0, const float* __restrict__ Wr0,
                                  const float* __restrict__ Wl1, const float* __restrict__ Wr1,
                                  const float* __restrict__ Wl2, const float* __restrict__ Wr2) {
    const int gs = gridDim.x * blockDim.x;
    const int t0 = blockIdx.x * blockDim.x + threadIdx.x;
    for (int i = t0; i < NN * DD / 2; i += gs) {
        float2 v = ((const float2*)x)[i];
        ((__half2*)g_xh)[i] = __floats2half2_rn(v.x, v.y);
    }
    for (int i = t0; i < 3 * 128 * 256; i += gs) {
        int l = i >> 15;
        int j = i & 32767;
        int n = j >> 8, k = j & 255;
        const float* Wl = (l == 0) ? Wl0 : (l == 1 ? Wl1 : Wl2);
        const float* Wr = (l == 0) ? Wr0 : (l == 1 ? Wr1 : Wr2);
        float v = (k < 128) ? Wl[n * 128 + k] : Wr[n * 128 + (k - 128)];
        g_Bh[i] = __float2half_rn(v);
    }
}

// ---------------- side stream: batch conversion + per-graph counts ----------------
__global__ void batch_cnt_kernel(const void* __restrict__ b) {
    __shared__ float scnt[GG];
    const int t = threadIdx.x;
    const int i = blockIdx.x * 256 + t;
    scnt[t] = 0.f; scnt[t + 256] = 0.f;
    __syncthreads();
    if (i < NN) {
        const int is64 = g_is64;
        int g = is64 ? (int)((const long long*)b)[i] : ((const int*)b)[i];
        g_batch[i] = g;
        atomicAdd(&scnt[g], 1.f);
    }
    __syncthreads();
    if (scnt[t] != 0.f) atomicAdd(&g_cnt[t], scnt[t]);
    if (scnt[t + 256] != 0.f) atomicAdd(&g_cnt[t + 256], scnt[t + 256]);
}

// ---------------- scan for CSR ----------------
__global__ void scan_part1_kernel() {
    __shared__ int sh[256];
    const int t = threadIdx.x;
    const int i = blockIdx.x * 256 + t;
    sh[t] = (i < NN) ? g_deg[i] : 0;
    __syncthreads();
    for (int o = 128; o; o >>= 1) {
        if (t < o) sh[t] += sh[t + o];
        __syncthreads();
    }
    if (t == 0) g_blocksum[blockIdx.x] = sh[0];
}

// scan3 with scan2 absorbed: every block redundantly scans the 196 block sums
__global__ void scan_part3_kernel() {
    __shared__ int sb[256];
    __shared__ int sh[256];
    int t = threadIdx.x;
    sb[t] = (t < NB) ? g_blocksum[t] : 0;
    __syncthreads();
    for (int o = 1; o < 256; o <<= 1) {
        int v = (t >= o) ? sb[t - o] : 0;
        __syncthreads();
        sb[t] += v;
        __syncthreads();
    }
    int blockoff = (blockIdx.x == 0) ? 0 : sb[blockIdx.x - 1];
    int i = blockIdx.x * 256 + t;
    int v = (i < NN) ? g_deg[i] : 0;
    sh[t] = v;
    __syncthreads();
    for (int o = 1; o < 256; o <<= 1) {
        int u = (t >= o) ? sh[t - o] : 0;
        __syncthreads();
        sh[t] += u;
        __syncthreads();
    }
    if (i < NN) {
        int excl = sh[t] - v + blockoff;
        g_rowptr[i] = excl;
        g_cursor[i] = excl;
        g_invdeg[i] = 1.f / fmaxf((float)v, 1.f);
    }
}

// place edges directly from ei (no staging buffers)
__global__ void place_edges_kernel(const void* __restrict__ ei) {
    const int is64 = g_is64;
    const long long* p64 = (const long long*)ei;
    const int*       p32 = (const int*)ei;
    for (int i = blockIdx.x * blockDim.x + threadIdx.x; i < EE; i += gridDim.x * blockDim.x) {
        int s, d;
        if (is64) { s = (int)p64[i]; d = (int)p64[EE + i]; }
        else      { s = p32[i];      d = p32[EE + i]; }
        int pos = atomicAdd(&g_cursor[d], 1);
        g_esrc[pos] = s;
    }
}

// ---------------- gather mean -> g_aggh: 2 edges per LDG.128, register-broadcast indices ----------------
__global__ __launch_bounds__(256) void gather_kernel() {
    const unsigned FULL = 0xffffffffu;
    int node = (blockIdx.x * 256 + threadIdx.x) >> 5;
    if (node >= NN) return;
    const int lane = threadIdx.x & 31;
    const int hw = lane >> 4;
    const int sub = lane & 15;
    const int beg = g_rowptr[node];
    const int end = beg + g_deg[node];

    float a0 = 0.f, a1 = 0.f, a2 = 0.f, a3 = 0.f, a4 = 0.f, a5 = 0.f, a6 = 0.f, a7 = 0.f;
    int e = beg;

#define ACC_ROW(vv) do { \
        float2 p; \
        p = __half22float2(*(__half2*)&(vv).x); a0 += p.x; a1 += p.y; \
        p = __half22float2(*(__half2*)&(vv).y); a2 += p.x; a3 += p.y; \
        p = __half22float2(*(__half2*)&(vv).z); a4 += p.x; a5 += p.y; \
        p = __half22float2(*(__half2*)&(vv).w); a6 += p.x; a7 += p.y; \
    } while (0)

    int pre = (4 - (beg & 3)) & 3;
    if (pre > end - beg) pre = end - beg;
#pragma unroll 1
    for (int q = 0; q < pre; q++, e++) {
        int s = g_esrc[e];
        if (hw == 0) {
            uint4 v = __ldg((const uint4*)g_xh + (size_t)s * 16 + sub);
            ACC_ROW(v);
        }
    }
#pragma unroll 1
    for (; e + 8 <= end; e += 8) {
        int4 ia = *(const int4*)(g_esrc + e);
        int4 ib = *(const int4*)(g_esrc + e + 4);
        int s0 = hw ? ia.y : ia.x;
        int s1 = hw ? ia.w : ia.z;
        int s2 = hw ? ib.y : ib.x;
        int s3 = hw ? ib.w : ib.z;
        uint4 v0 = __ldg((const uint4*)g_xh + (size_t)s0 * 16 + sub);
        uint4 v1 = __ldg((const uint4*)g_xh + (size_t)s1 * 16 + sub);
        uint4 v2 = __ldg((const uint4*)g_xh + (size_t)s2 * 16 + sub);
        uint4 v3 = __ldg((const uint4*)g_xh + (size_t)s3 * 16 + sub);
        ACC_ROW(v0); ACC_ROW(v1); ACC_ROW(v2); ACC_ROW(v3);
    }
#pragma unroll 1
    for (; e + 2 <= end; e += 2) {
        int sa = g_esrc[e], sbb = g_esrc[e + 1];
        int s = hw ? sbb : sa;
        uint4 v = __ldg((const uint4*)g_xh + (size_t)s * 16 + sub);
        ACC_ROW(v);
    }
    if (e < end) {
        int s = g_esrc[e];
        if (hw == 0) {
            uint4 v = __ldg((const uint4*)g_xh + (size_t)s * 16 + sub);
            ACC_ROW(v);
        }
    }
#undef ACC_ROW

    a0 += __shfl_xor_sync(FULL, a0, 16);
    a1 += __shfl_xor_sync(FULL, a1, 16);
    a2 += __shfl_xor_sync(FULL, a2, 16);
    a3 += __shfl_xor_sync(FULL, a3, 16);
    a4 += __shfl_xor_sync(FULL, a4, 16);
    a5 += __shfl_xor_sync(FULL, a5, 16);
    a6 += __shfl_xor_sync(FULL, a6, 16);
    a7 += __shfl_xor_sync(FULL, a7, 16);

    if (hw == 0) {
        float inv = g_invdeg[node];
        __half2 h0 = __floats2half2_rn(a0 * inv, a1 * inv);
        __half2 h1 = __floats2half2_rn(a2 * inv, a3 * inv);
        __half2 h2 = __floats2half2_rn(a4 * inv, a5 * inv);
        __half2 h3 = __floats2half2_rn(a6 * inv, a7 * inv);
        uint4 st;
        st.x = *(unsigned int*)&h0;
        st.y = *(unsigned int*)&h1;
        st.z = *(unsigned int*)&h2;
        st.w = *(unsigned int*)&h3;
        *((uint4*)g_aggh + (size_t)node * 16 + sub) = st;
    }
}

// ---------------- combine via single fp16 mma.sync: Y = relu([aggh|xh] @ W^T + b) ----------------
#define MMAF16(d, a, b0_, b1_) \
    asm volatile("mma.sync.aligned.m16n8k16.row.col.f32.f16.f16.f32 " \
                 "{%0,%1,%2,%3},{%4,%5,%6,%7},{%8,%9},{%0,%1,%2,%3};" \
                 : "+f"(d[0]), "+f"(d[1]), "+f"(d[2]), "+f"(d[3]) \
                 : "r"(a[0]), "r"(a[1]), "r"(a[2]), "r"(a[3]), "r"(b0_), "r"(b1_))

__global__ __launch_bounds__(256, 2) void combine_kernel(
    int layer, const float* __restrict__ bias, const float* __restrict__ fcw, int do_pool)
{
    const __half* __restrict__ Bh = g_Bh + layer * 128 * 256;

    __shared__ __half sA[128 * 36];
    __shared__ __half sB[128 * 36];
    __shared__ float sdot[128];

    const int tid = threadIdx.x;
    const int lane = tid & 31;
    const int warp = tid >> 5;
    const int wm = warp & 3;
    const int wn = warp >> 2;
    const int row0 = blockIdx.x * 128;
    const int gr = lane >> 2;
    const int tg2 = (lane & 3) * 2;

    if (do_pool && tid < 128) sdot[tid] = 0.f;

    float acc[2][8][4];
#pragma unroll
    for (int mt = 0; mt < 2; mt++)
#pragma unroll
        for (int nt = 0; nt < 8; nt++)
#pragma unroll
            for (int q = 0; q < 4; q++) acc[mt][nt][q] = 0.f;

#pragma unroll 1
    for (int c = 0; c < 8; c++) {
        const int k0 = c * 32;
        const bool from_x = (k0 >= 128);
        const __half* __restrict__ Asrc = from_x ? g_xh : g_aggh;
        const int kb = from_x ? (k0 - 128) : k0;
#pragma unroll
        for (int it = 0; it < 4; it++) {
            int s = tid + it * 256;
            int r = s >> 3;
            int c4 = (s & 7) * 4;
            int grow = row0 + r; if (grow >= NN) grow = NN - 1;
            *(uint2*)&sA[r * 36 + c4] = *(const uint2*)&Asrc[(size_t)grow * DD + kb + c4];
            *(uint2*)&sB[r * 36 + c4] = *(const uint2*)&Bh[r * 256 + k0 + c4];
        }
        __syncthreads();

#pragma unroll
        for (int kk = 0; kk < 32; kk += 16) {
            unsigned int a[2][4];
#pragma unroll
            for (int mt = 0; mt < 2; mt++) {
                int rb = wm * 32 + mt * 16;
                a[mt][0] = *(const unsigned int*)&sA[(rb + gr) * 36 + kk + tg2];
                a[mt][1] = *(const unsigned int*)&sA[(rb + gr + 8) * 36 + kk + tg2];
                a[mt][2] = *(const unsigned int*)&sA[(rb + gr) * 36 + kk + tg2 + 8];
                a[mt][3] = *(const unsigned int*)&sA[(rb + gr + 8) * 36 + kk + tg2 + 8];
            }
#pragma unroll
            for (int nt = 0; nt < 8; nt++) {
                int nb = wn * 64 + nt * 8 + gr;
                unsigned int b0 = *(const unsigned int*)&sB[nb * 36 + kk + tg2];
                unsigned int b1 = *(const unsigned int*)&sB[nb * 36 + kk + tg2 + 8];
#pragma unroll
                for (int mt = 0; mt < 2; mt++) {
                    MMAF16(acc[mt][nt], a[mt], b0, b1);
                }
            }
        }
        __syncthreads();
    }

    // ---- epilogue ----
    if (!do_pool) {
#pragma unroll
        for (int mt = 0; mt < 2; mt++) {
#pragma unroll
            for (int nt = 0; nt < 8; nt++) {
                int col = wn * 64 + nt * 8 + tg2;
                float b0 = bias[col], b1 = bias[col + 1];
#pragma unroll
                for (int half = 0; half < 2; half++) {
                    int row = row0 + wm * 32 + mt * 16 + gr + half * 8;
                    if (row >= NN) continue;
                    float v0 = fmaxf(acc[mt][nt][half * 2 + 0] + b0, 0.f);
                    float v1 = fmaxf(acc[mt][nt][half * 2 + 1] + b1, 0.f);
                    *(__half2*)&g_xh[(size_t)row * DD + col] = __floats2half2_rn(v0, v1);
                }
            }
        }
    } else {
#pragma unroll
        for (int mt = 0; mt < 2; mt++) {
#pragma unroll
            for (int nt = 0; nt < 8; nt++) {
                int col = wn * 64 + nt * 8 + tg2;
                float b0 = bias[col], b1 = bias[col + 1];
                float w0 = fcw[col], w1 = fcw[col + 1];
#pragma unroll
                for (int half = 0; half < 2; half++) {
                    int lr = wm * 32 + mt * 16 + gr + half * 8;
                    float v0 = fmaxf(acc[mt][nt][half * 2 + 0] + b0, 0.f);
                    float v1 = fmaxf(acc[mt][nt][half * 2 + 1] + b1, 0.f);
                    atomicAdd(&sdot[lr], v0 * w0 + v1 * w1);
                }
            }
        }
        __syncthreads();
        if (tid < 128) {
            int grow = row0 + tid;
            if (grow < NN) atomicAdd(&g_acc[g_batch[grow]], sdot[tid]);
        }
    }
}

__global__ void final_kernel(float* __restrict__ out, const float* __restrict__ fcb) {
    int g = blockIdx.x * blockDim.x + threadIdx.x;
    if (g < GG) out[g] = g_acc[g] / fmaxf(g_cnt[g], 1.f) + fcb[0];
}

// ---------------- launch ----------------
extern "C" void kernel_launch(void* const* d_in, const int* in_sizes, int n_in,
                              void* d_out, int out_size) {
    const float* x     = (const float*)d_in[0];
    const void*  ei    = d_in[1];
    const void*  batch = d_in[2];
    const float* Wl[3] = {(const float*)d_in[3], (const float*)d_in[6], (const float*)d_in[9]};
    const float* bb[3] = {(const float*)d_in[4], (const float*)d_in[7], (const float*)d_in[10]};
    const float* Wr[3] = {(const float*)d_in[5], (const float*)d_in[8], (const float*)d_in[11]};
    const float* fcw = (const float*)d_in[12];
    const float* fcb = (const float*)d_in[13];
    float* out = (float*)d_out;

    // one-time host-side infra (no device allocations)
    static cudaStream_t s_side = nullptr;
    static cudaEvent_t ev_fork = nullptr, ev_join = nullptr;
    if (!s_side) {
        cudaStreamCreateWithFlags(&s_side, cudaStreamNonBlocking);
        cudaEventCreateWithFlags(&ev_fork, cudaEventDisableTiming);
        cudaEventCreateWithFlags(&ev_join, cudaEventDisableTiming);
    }

    // prep: critical path on main stream, independent conversions forked to side stream
    init_kernel<<<NB, 256>>>(ei);
    cudaEventRecord(ev_fork, 0);
    cudaStreamWaitEvent(s_side, ev_fork, 0);
    convert_xw_kernel<<<1024, 256, 0, s_side>>>(x, Wl[0], Wr[0], Wl[1], Wr[1], Wl[2], Wr[2]);
    batch_cnt_kernel<<<NB, 256, 0, s_side>>>(batch);
    cudaEventRecord(ev_join, s_side);

    deg_hist_kernel<<<2048, 256>>>(ei);
    scan_part1_kernel<<<NB, 256>>>();
    scan_part3_kernel<<<NB, 256>>>();
    place_edges_kernel<<<4096, 256>>>(ei);
    cudaStreamWaitEvent(0, ev_join, 0);

    const int gather_blocks = (NN * 32 + 255) / 256;

    // layer 0
    gather_kernel<<<gather_blocks, 256>>>();
    combine_kernel<<<CBLK, 256>>>(0, bb[0], fcw, 0);
    // layer 1
    gather_kernel<<<gather_blocks, 256>>>();
    combine_kernel<<<CBLK, 256>>>(1, bb[1], fcw, 0);
    // layer 2: pooled dots
    gather_kernel<<<gather_blocks, 256>>>();
    combine_kernel<<<CBLK, 256>>>(2, bb[2], fcw, 1);

    final_kernel<<<(GG + 255) / 256, 256>>>(out, fcb);
}

// round 16
// speedup vs baseline: 1.4990x; 1.0068x over previous
#include <cuda_runtime.h>
#include <cuda_fp16.h>

#define NN 50000
#define EE 1600000
#define DD 128
#define GG 512
#define NB 196          // ceil(NN/256)
#define CBLK 391        // ceil(NN/128)

// ---------------- scratch (static device globals; no allocation) ----------------
__device__ __half g_aggh[NN * DD];           // fp16 mean-aggregated features
__device__ __half g_xh[NN * DD];             // fp16 current layer features
__device__ __half g_Bh[3 * 128 * 256];       // W fp16
__device__ float g_invdeg[NN];
__device__ int   g_deg[NN];
__device__ int   g_rowptr[NN];
__device__ int   g_cursor[NN];
__device__ int   g_esrc[EE];
__device__ int   g_batch[NN];
__device__ float g_acc[GG];
__device__ float g_cnt[GG];
__device__ int   g_base;                     // scan segment allocator
__device__ int   g_is64;

// ---------------- init: zero scratch + dtype probe (one launch) ----------------
__global__ void init_kernel(const void* __restrict__ ei) {
    int i = blockIdx.x * blockDim.x + threadIdx.x;
    if (i < NN) g_deg[i] = 0;
    if (i < GG) { g_acc[i] = 0.f; g_cnt[i] = 0.f; }
    if (i == 0) {
        g_base = 0;
        const long long* p = (const long long*)ei;
        int ok = 1;
#pragma unroll 1
        for (int j = 0; j < 64; j++) {
            long long v = p[j];
            if (v < 0 || v >= NN) ok = 0;
        }
        g_is64 = ok;
    }
}

// ---------------- deg histogram (critical path) ----------------
__global__ void deg_hist_kernel(const void* __restrict__ ei) {
    const int is64 = g_is64;
    const long long* p64 = (const long long*)ei;
    const int*       p32 = (const int*)ei;
    for (int i = blockIdx.x * blockDim.x + threadIdx.x; i < EE; i += gridDim.x * blockDim.x) {
        int d = is64 ? (int)p64[EE + i] : p32[EE + i];
        atomicAdd(&g_deg[d], 1);
    }
}

// ---------------- side stream: x->fp16 + weights->fp16 ----------------
__global__ void convert_xw_kernel(const float* __restrict__ x,
                                  const float* __restrict__ Wl0, const float* __restrict__ Wr0,
                                  const float* __restrict__ Wl1, const float* __restrict__ Wr1,
                                  const float* __restrict__ Wl2, const float* __restrict__ Wr2) {
    const int gs = gridDim.x * blockDim.x;
    const int t0 = blockIdx.x * blockDim.x + threadIdx.x;
    for (int i = t0; i < NN * DD / 2; i += gs) {
        float2 v = ((const float2*)x)[i];
        ((__half2*)g_xh)[i] = __floats2half2_rn(v.x, v.y);
    }
    for (int i = t0; i < 3 * 128 * 256; i += gs) {
        int l = i >> 15;
        int j = i & 32767;
        int n = j >> 8, k = j & 255;
        const float* Wl = (l == 0) ? Wl0 : (l == 1 ? Wl1 : Wl2);
        const float* Wr = (l == 0) ? Wr0 : (l == 1 ? Wr1 : Wr2);
        float v = (k < 128) ? Wl[n * 128 + k] : Wr[n * 128 + (k - 128)];
        g_Bh[i] = __float2half_rn(v);
    }
}

// ---------------- side stream: batch conversion + per-graph counts ----------------
__global__ void batch_cnt_kernel(const void* __restrict__ b) {
    __shared__ float scnt[GG];
    const int t = threadIdx.x;
    const int i = blockIdx.x * 256 + t;
    scnt[t] = 0.f; scnt[t + 256] = 0.f;
    __syncthreads();
    if (i < NN) {
        const int is64 = g_is64;
        int g = is64 ? (int)((const long long*)b)[i] : ((const int*)b)[i];
        g_batch[i] = g;
        atomicAdd(&scnt[g], 1.f);
    }
    __syncthreads();
    if (scnt[t] != 0.f) atomicAdd(&g_cnt[t], scnt[t]);
    if (scnt[t + 256] != 0.f) atomicAdd(&g_cnt[t + 256], scnt[t + 256]);
}

// ---------------- single-kernel scan: order-independent block-base allocation ----------------
__global__ void scan_kernel() {
    __shared__ int sh[256];
    __shared__ int sbase;
    const int t = threadIdx.x;
    const int i = blockIdx.x * 256 + t;
    int v = (i < NN) ? g_deg[i] : 0;
    sh[t] = v;
    __syncthreads();
    for (int o = 1; o < 256; o <<= 1) {
        int u = (t >= o) ? sh[t - o] : 0;
        __syncthreads();
        sh[t] += u;
        __syncthreads();
    }
    if (t == 255) sbase = atomicAdd(&g_base, sh[255]);
    __syncthreads();
    if (i < NN) {
        int excl = sh[t] - v + sbase;
        g_rowptr[i] = excl;
        g_cursor[i] = excl;
        g_invdeg[i] = 1.f / fmaxf((float)v, 1.f);
    }
}

// place edges directly from ei (no staging buffers)
__global__ void place_edges_kernel(const void* __restrict__ ei) {
    const int is64 = g_is64;
    const long long* p64 = (const long long*)ei;
    const int*       p32 = (const int*)ei;
    for (int i = blockIdx.x * blockDim.x + threadIdx.x; i < EE; i += gridDim.x * blockDim.x) {
        int s, d;
        if (is64) { s = (int)p64[i]; d = (int)p64[EE + i]; }
        else      { s = p32[i];      d = p32[EE + i]; }
        int pos = atomicAdd(&g_cursor[d], 1);
        g_esrc[pos] = s;
    }
}

// ---------------- gather mean -> g_aggh: 2 edges per LDG.128, register-broadcast indices ----------------
__global__ __launch_bounds__(256) void gather_kernel() {
    const unsigned FULL = 0xffffffffu;
    int node = (blockIdx.x * 256 + threadIdx.x) >> 5;
    if (node >= NN) return;
    const int lane = threadIdx.x & 31;
    const int hw = lane >> 4;
    const int sub = lane & 15;
    const int beg = g_rowptr[node];
    const int end = beg + g_deg[node];

    float a0 = 0.f, a1 = 0.f, a2 = 0.f, a3 = 0.f, a4 = 0.f, a5 = 0.f, a6 = 0.f, a7 = 0.f;
    int e = beg;

#define ACC_ROW(vv) do { \
        float2 p; \
        p = __half22float2(*(__half2*)&(vv).x); a0 += p.x; a1 += p.y; \
        p = __half22float2(*(__half2*)&(vv).y); a2 += p.x; a3 += p.y; \
        p = __half22float2(*(__half2*)&(vv).z); a4 += p.x; a5 += p.y; \
        p = __half22float2(*(__half2*)&(vv).w); a6 += p.x; a7 += p.y; \
    } while (0)

    int pre = (4 - (beg & 3)) & 3;
    if (pre > end - beg) pre = end - beg;
#pragma unroll 1
    for (int q = 0; q < pre; q++, e++) {
        int s = g_esrc[e];
        if (hw == 0) {
            uint4 v = __ldg((const uint4*)g_xh + (size_t)s * 16 + sub);
            ACC_ROW(v);
        }
    }
#pragma unroll 1
    for (; e + 8 <= end; e += 8) {
        int4 ia = *(const int4*)(g_esrc + e);
        int4 ib = *(const int4*)(g_esrc + e + 4);
        int s0 = hw ? ia.y : ia.x;
        int s1 = hw ? ia.w : ia.z;
        int s2 = hw ? ib.y : ib.x;
        int s3 = hw ? ib.w : ib.z;
        uint4 v0 = __ldg((const uint4*)g_xh + (size_t)s0 * 16 + sub);
        uint4 v1 = __ldg((const uint4*)g_xh + (size_t)s1 * 16 + sub);
        uint4 v2 = __ldg((const uint4*)g_xh + (size_t)s2 * 16 + sub);
        uint4 v3 = __ldg((const uint4*)g_xh + (size_t)s3 * 16 + sub);
        ACC_ROW(v0); ACC_ROW(v1); ACC_ROW(v2); ACC_ROW(v3);
    }
#pragma unroll 1
    for (; e + 2 <= end; e += 2) {
        int sa = g_esrc[e], sbb = g_esrc[e + 1];
        int s = hw ? sbb : sa;
        uint4 v = __ldg((const uint4*)g_xh + (size_t)s * 16 + sub);
        ACC_ROW(v);
    }
    if (e < end) {
        int s = g_esrc[e];
        if (hw == 0) {
            uint4 v = __ldg((const uint4*)g_xh + (size_t)s * 16 + sub);
            ACC_ROW(v);
        }
    }
#undef ACC_ROW

    a0 += __shfl_xor_sync(FULL, a0, 16);
    a1 += __shfl_xor_sync(FULL, a1, 16);
    a2 += __shfl_xor_sync(FULL, a2, 16);
    a3 += __shfl_xor_sync(FULL, a3, 16);
    a4 += __shfl_xor_sync(FULL, a4, 16);
    a5 += __shfl_xor_sync(FULL, a5, 16);
    a6 += __shfl_xor_sync(FULL, a6, 16);
    a7 += __shfl_xor_sync(FULL, a7, 16);

    if (hw == 0) {
        float inv = g_invdeg[node];
        __half2 h0 = __floats2half2_rn(a0 * inv, a1 * inv);
        __half2 h1 = __floats2half2_rn(a2 * inv, a3 * inv);
        __half2 h2 = __floats2half2_rn(a4 * inv, a5 * inv);
        __half2 h3 = __floats2half2_rn(a6 * inv, a7 * inv);
        uint4 st;
        st.x = *(unsigned int*)&h0;
        st.y = *(unsigned int*)&h1;
        st.z = *(unsigned int*)&h2;
        st.w = *(unsigned int*)&h3;
        *((uint4*)g_aggh + (size_t)node * 16 + sub) = st;
    }
}

// ---------------- combine via single fp16 mma.sync: Y = relu([aggh|xh] @ W^T + b) ----------------
#define MMAF16(d, a, b0_, b1_) \
    asm volatile("mma.sync.aligned.m16n8k16.row.col.f32.f16.f16.f32 " \
                 "{%0,%1,%2,%3},{%4,%5,%6,%7},{%8,%9},{%0,%1,%2,%3};" \
                 : "+f"(d[0]), "+f"(d[1]), "+f"(d[2]), "+f"(d[3]) \
                 : "r"(a[0]), "r"(a[1]), "r"(a[2]), "r"(a[3]), "r"(b0_), "r"(b1_))

__global__ __launch_bounds__(256, 2) void combine_kernel(
    int layer, const float* __restrict__ bias, const float* __restrict__ fcw, int do_pool)
{
    const __half* __restrict__ Bh = g_Bh + layer * 128 * 256;

    __shared__ __half sA[128 * 36];
    __shared__ __half sB[128 * 36];
    __shared__ float sdot[128];

    const int tid = threadIdx.x;
    const int lane = tid & 31;
    const int warp = tid >> 5;
    const int wm = warp & 3;
    const int wn = warp >> 2;
    const int row0 = blockIdx.x * 128;
    const int gr = lane >> 2;
    const int tg2 = (lane & 3) * 2;

    if (do_pool && tid < 128) sdot[tid] = 0.f;

    float acc[2][8][4];
#pragma unroll
    for (int mt = 0; mt < 2; mt++)
#pragma unroll
        for (int nt = 0; nt < 8; nt++)
#pragma unroll
            for (int q = 0; q < 4; q++) acc[mt][nt][q] = 0.f;

#pragma unroll 1
    for (int c = 0; c < 8; c++) {
        const int k0 = c * 32;
        const bool from_x = (k0 >= 128);
        const __half* __restrict__ Asrc = from_x ? g_xh : g_aggh;
        const int kb = from_x ? (k0 - 128) : k0;
#pragma unroll
        for (int it = 0; it < 4; it++) {
            int s = tid + it * 256;
            int r = s >> 3;
            int c4 = (s & 7) * 4;
            int grow = row0 + r; if (grow >= NN) grow = NN - 1;
            *(uint2*)&sA[r * 36 + c4] = *(const uint2*)&Asrc[(size_t)grow * DD + kb + c4];
            *(uint2*)&sB[r * 36 + c4] = *(const uint2*)&Bh[r * 256 + k0 + c4];
        }
        __syncthreads();

#pragma unroll
        for (int kk = 0; kk < 32; kk += 16) {
            unsigned int a[2][4];
#pragma unroll
            for (int mt = 0; mt < 2; mt++) {
                int rb = wm * 32 + mt * 16;
                a[mt][0] = *(const unsigned int*)&sA[(rb + gr) * 36 + kk + tg2];
                a[mt][1] = *(const unsigned int*)&sA[(rb + gr + 8) * 36 + kk + tg2];
                a[mt][2] = *(const unsigned int*)&sA[(rb + gr) * 36 + kk + tg2 + 8];
                a[mt][3] = *(const unsigned int*)&sA[(rb + gr + 8) * 36 + kk + tg2 + 8];
            }
#pragma unroll
            for (int nt = 0; nt < 8; nt++) {
                int nb = wn * 64 + nt * 8 + gr;
                unsigned int b0 = *(const unsigned int*)&sB[nb * 36 + kk + tg2];
                unsigned int b1 = *(const unsigned int*)&sB[nb * 36 + kk + tg2 + 8];
#pragma unroll
                for (int mt = 0; mt < 2; mt++) {
                    MMAF16(acc[mt][nt], a[mt], b0, b1);
                }
            }
        }
        __syncthreads();
    }

    // ---- epilogue ----
    if (!do_pool) {
#pragma unroll
        for (int mt = 0; mt < 2; mt++) {
#pragma unroll
            for (int nt = 0; nt < 8; nt++) {
                int col = wn * 64 + nt * 8 + tg2;
                float b0 = bias[col], b1 = bias[col + 1];
#pragma unroll
                for (int half = 0; half < 2; half++) {
                    int row = row0 + wm * 32 + mt * 16 + gr + half * 8;
                    if (row >= NN) continue;
                    float v0 = fmaxf(acc[mt][nt][half * 2 + 0] + b0, 0.f);
                    float v1 = fmaxf(acc[mt][nt][half * 2 + 1] + b1, 0.f);
                    *(__half2*)&g_xh[(size_t)row * DD + col] = __floats2half2_rn(v0, v1);
                }
            }
        }
    } else {
#pragma unroll
        for (int mt = 0; mt < 2; mt++) {
#pragma unroll
            for (int nt = 0; nt < 8; nt++) {
                int col = wn * 64 + nt * 8 + tg2;
                float b0 = bias[col], b1 = bias[col + 1];
                float w0 = fcw[col], w1 = fcw[col + 1];
#pragma unroll
                for (int half = 0; half < 2; half++) {
                    int lr = wm * 32 + mt * 16 + gr + half * 8;
                    float v0 = fmaxf(acc[mt][nt][half * 2 + 0] + b0, 0.f);
                    float v1 = fmaxf(acc[mt][nt][half * 2 + 1] + b1, 0.f);
                    atomicAdd(&sdot[lr], v0 * w0 + v1 * w1);
                }
            }
        }
        __syncthreads();
        if (tid < 128) {
            int grow = row0 + tid;
            if (grow < NN) atomicAdd(&g_acc[g_batch[grow]], sdot[tid]);
        }
    }
}

__global__ void final_kernel(float* __restrict__ out, const float* __restrict__ fcb) {
    int g = blockIdx.x * blockDim.x + threadIdx.x;
    if (g < GG) out[g] = g_acc[g] / fmaxf(g_cnt[g], 1.f) + fcb[0];
}

// ---------------- launch ----------------
extern "C" void kernel_launch(void* const* d_in, const int* in_sizes, int n_in,
                              void* d_out, int out_size) {
    const float* x     = (const float*)d_in[0];
    const void*  ei    = d_in[1];
    const void*  batch = d_in[2];
    const float* Wl[3] = {(const float*)d_in[3], (const float*)d_in[6], (const float*)d_in[9]};
    const float* bb[3] = {(const float*)d_in[4], (const float*)d_in[7], (const float*)d_in[10]};
    const float* Wr[3] = {(const float*)d_in[5], (const float*)d_in[8], (const float*)d_in[11]};
    const float* fcw = (const float*)d_in[12];
    const float* fcb = (const float*)d_in[13];
    float* out = (float*)d_out;

    // one-time host-side infra (no device allocations)
    static cudaStream_t s_side = nullptr;
    static cudaEvent_t ev_fork = nullptr, ev_join = nullptr;
    if (!s_side) {
        cudaStreamCreateWithFlags(&s_side, cudaStreamNonBlocking);
        cudaEventCreateWithFlags(&ev_fork, cudaEventDisableTiming);
        cudaEventCreateWithFlags(&ev_join, cudaEventDisableTiming);
    }

    // prep: critical path on main stream, independent conversions forked to side stream
    init_kernel<<<NB, 256>>>(ei);
    cudaEventRecord(ev_fork, 0);
    cudaStreamWaitEvent(s_side, ev_fork, 0);
    convert_xw_kernel<<<1024, 256, 0, s_side>>>(x, Wl[0], Wr[0], Wl[1], Wr[1], Wl[2], Wr[2]);
    batch_cnt_kernel<<<NB, 256, 0, s_side>>>(batch);
    cudaEventRecord(ev_join, s_side);

    deg_hist_kernel<<<2048, 256>>>(ei);
    scan_kernel<<<NB, 256>>>();
    place_edges_kernel<<<4096, 256>>>(ei);
    cudaStreamWaitEvent(0, ev_join, 0);

    const int gather_blocks = (NN * 32 + 255) / 256;

    // layer 0
    gather_kernel<<<gather_blocks, 256>>>();
    combine_kernel<<<CBLK, 256>>>(0, bb[0], fcw, 0);
    // layer 1
    gather_kernel<<<gather_blocks, 256>>>();
    combine_kernel<<<CBLK, 256>>>(1, bb[1], fcw, 0);
    // layer 2: pooled dots
    gather_kernel<<<gather_blocks, 256>>>();
    combine_kernel<<<CBLK, 256>>>(2, bb[2], fcw, 1);

    final_kernel<<<(GG + 255) / 256, 256>>>(out, fcb);
}

// round 17
// speedup vs baseline: 1.5009x; 1.0012x over previous
#include <cuda_runtime.h>
#include <cuda_fp16.h>

#define NN 50000
#define EE 1600000
#define DD 128
#define GG 512
#define NB 196          // ceil(NN/256)
#define CBLK 391        // ceil(NN/128)
#define EB4 1563        // ceil(EE/4/256): one 4-edge chunk per thread

// ---------------- scratch (static device globals; no allocation) ----------------
__device__ __half g_aggh[NN * DD];           // fp16 mean-aggregated features
__device__ __half g_xh[NN * DD];             // fp16 current layer features
__device__ __half g_Bh[3 * 128 * 256];       // W fp16
__device__ float g_invdeg[NN];
__device__ int   g_deg[NN];
__device__ int   g_rowptr[NN];
__device__ int   g_cursor[NN];
__device__ int   g_esrc[EE];
__device__ int   g_batch[NN];
__device__ float g_acc[GG];
__device__ float g_cnt[GG];
__device__ int   g_base;                     // scan segment allocator
__device__ int   g_is64;

// ---------------- init: zero scratch + dtype probe (one launch) ----------------
__global__ void init_kernel(const void* __restrict__ ei) {
    int i = blockIdx.x * blockDim.x + threadIdx.x;
    if (i < NN) g_deg[i] = 0;
    if (i < GG) { g_acc[i] = 0.f; g_cnt[i] = 0.f; }
    if (i == 0) {
        g_base = 0;
        const long long* p = (const long long*)ei;
        int ok = 1;
#pragma unroll 1
        for (int j = 0; j < 64; j++) {
            long long v = p[j];
            if (v < 0 || v >= NN) ok = 0;
        }
        g_is64 = ok;
    }
}

// ---------------- deg histogram: 4 consecutive edges per thread, batched loads ----------------
__global__ void deg_hist_kernel(const void* __restrict__ ei) {
    const int is64 = g_is64;
    const long long* p64 = (const long long*)ei;
    const int*       p32 = (const int*)ei;
    int i0 = (blockIdx.x * blockDim.x + threadIdx.x) * 4;
    if (i0 + 4 <= EE) {
        int d0, d1, d2, d3;
        if (is64) {
            longlong2 a = *(const longlong2*)(p64 + EE + i0);
            longlong2 b = *(const longlong2*)(p64 + EE + i0 + 2);
            d0 = (int)a.x; d1 = (int)a.y; d2 = (int)b.x; d3 = (int)b.y;
        } else {
            int4 a = *(const int4*)(p32 + EE + i0);
            d0 = a.x; d1 = a.y; d2 = a.z; d3 = a.w;
        }
        atomicAdd(&g_deg[d0], 1);
        atomicAdd(&g_deg[d1], 1);
        atomicAdd(&g_deg[d2], 1);
        atomicAdd(&g_deg[d3], 1);
    } else {
        for (int i = i0; i < EE; i++) {
            int d = is64 ? (int)p64[EE + i] : p32[EE + i];
            atomicAdd(&g_deg[d], 1);
        }
    }
}

// ---------------- side stream: x->fp16 + weights->fp16 ----------------
__global__ void convert_xw_kernel(const float* __restrict__ x,
                                  const float* __restrict__ Wl0, const float* __restrict__ Wr0,
                                  const float* __restrict__ Wl1, const float* __restrict__ Wr1,
                                  const float* __restrict__ Wl2, const float* __restrict__ Wr2) {
    const int gs = gridDim.x * blockDim.x;
    const int t0 = blockIdx.x * blockDim.x + threadIdx.x;
    for (int i = t0; i < NN * DD / 2; i += gs) {
        float2 v = ((const float2*)x)[i];
        ((__half2*)g_xh)[i] = __floats2half2_rn(v.x, v.y);
    }
    for (int i = t0; i < 3 * 128 * 256; i += gs) {
        int l = i >> 15;
        int j = i & 32767;
        int n = j >> 8, k = j & 255;
        const float* Wl = (l == 0) ? Wl0 : (l == 1 ? Wl1 : Wl2);
        const float* Wr = (l == 0) ? Wr0 : (l == 1 ? Wr1 : Wr2);
        float v = (k < 128) ? Wl[n * 128 + k] : Wr[n * 128 + (k - 128)];
        g_Bh[i] = __float2half_rn(v);
    }
}

// ---------------- side stream: batch conversion + per-graph counts ----------------
__global__ void batch_cnt_kernel(const void* __restrict__ b) {
    __shared__ float scnt[GG];
    const int t = threadIdx.x;
    const int i = blockIdx.x * 256 + t;
    scnt[t] = 0.f; scnt[t + 256] = 0.f;
    __syncthreads();
    if (i < NN) {
        const int is64 = g_is64;
        int g = is64 ? (int)((const long long*)b)[i] : ((const int*)b)[i];
        g_batch[i] = g;
        atomicAdd(&scnt[g], 1.f);
    }
    __syncthreads();
    if (scnt[t] != 0.f) atomicAdd(&g_cnt[t], scnt[t]);
    if (scnt[t + 256] != 0.f) atomicAdd(&g_cnt[t + 256], scnt[t + 256]);
}

// ---------------- single-kernel scan: order-independent block-base allocation ----------------
__global__ void scan_kernel() {
    __shared__ int sh[256];
    __shared__ int sbase;
    const int t = threadIdx.x;
    const int i = blockIdx.x * 256 + t;
    int v = (i < NN) ? g_deg[i] : 0;
    sh[t] = v;
    __syncthreads();
    for (int o = 1; o < 256; o <<= 1) {
        int u = (t >= o) ? sh[t - o] : 0;
        __syncthreads();
        sh[t] += u;
        __syncthreads();
    }
    if (t == 255) sbase = atomicAdd(&g_base, sh[255]);
    __syncthreads();
    if (i < NN) {
        int excl = sh[t] - v + sbase;
        g_rowptr[i] = excl;
        g_cursor[i] = excl;
        g_invdeg[i] = 1.f / fmaxf((float)v, 1.f);
    }
}

// ---------------- place edges: 4 consecutive edges per thread, batched loads ----------------
__global__ void place_edges_kernel(const void* __restrict__ ei) {
    const int is64 = g_is64;
    const long long* p64 = (const long long*)ei;
    const int*       p32 = (const int*)ei;
    int i0 = (blockIdx.x * blockDim.x + threadIdx.x) * 4;
    if (i0 + 4 <= EE) {
        int s0, s1, s2, s3, d0, d1, d2, d3;
        if (is64) {
            longlong2 sa = *(const longlong2*)(p64 + i0);
            longlong2 sb = *(const longlong2*)(p64 + i0 + 2);
            longlong2 da = *(const longlong2*)(p64 + EE + i0);
            longlong2 db = *(const longlong2*)(p64 + EE + i0 + 2);
            s0 = (int)sa.x; s1 = (int)sa.y; s2 = (int)sb.x; s3 = (int)sb.y;
            d0 = (int)da.x; d1 = (int)da.y; d2 = (int)db.x; d3 = (int)db.y;
        } else {
            int4 sa = *(const int4*)(p32 + i0);
            int4 da = *(const int4*)(p32 + EE + i0);
            s0 = sa.x; s1 = sa.y; s2 = sa.z; s3 = sa.w;
            d0 = da.x; d1 = da.y; d2 = da.z; d3 = da.w;
        }
        int q0 = atomicAdd(&g_cursor[d0], 1);
        int q1 = atomicAdd(&g_cursor[d1], 1);
        int q2 = atomicAdd(&g_cursor[d2], 1);
        int q3 = atomicAdd(&g_cursor[d3], 1);
        g_esrc[q0] = s0;
        g_esrc[q1] = s1;
        g_esrc[q2] = s2;
        g_esrc[q3] = s3;
    } else {
        for (int i = i0; i < EE; i++) {
            int s, d;
            if (is64) { s = (int)p64[i]; d = (int)p64[EE + i]; }
            else      { s = p32[i];      d = p32[EE + i]; }
            int pos = atomicAdd(&g_cursor[d], 1);
            g_esrc[pos] = s;
        }
    }
}

// ---------------- gather mean -> g_aggh: 2 edges per LDG.128, register-broadcast indices ----------------
__global__ __launch_bounds__(256) void gather_kernel() {
    const unsigned FULL = 0xffffffffu;
    int node = (blockIdx.x * 256 + threadIdx.x) >> 5;
    if (node >= NN) return;
    const int lane = threadIdx.x & 31;
    const int hw = lane >> 4;
    const int sub = lane & 15;
    const int beg = g_rowptr[node];
    const int end = beg + g_deg[node];

    float a0 = 0.f, a1 = 0.f, a2 = 0.f, a3 = 0.f, a4 = 0.f, a5 = 0.f, a6 = 0.f, a7 = 0.f;
    int e = beg;

#define ACC_ROW(vv) do { \
        float2 p; \
        p = __half22float2(*(__half2*)&(vv).x); a0 += p.x; a1 += p.y; \
        p = __half22float2(*(__half2*)&(vv).y); a2 += p.x; a3 += p.y; \
        p = __half22float2(*(__half2*)&(vv).z); a4 += p.x; a5 += p.y; \
        p = __half22float2(*(__half2*)&(vv).w); a6 += p.x; a7 += p.y; \
    } while (0)

    int pre = (4 - (beg & 3)) & 3;
    if (pre > end - beg) pre = end - beg;
#pragma unroll 1
    for (int q = 0; q < pre; q++, e++) {
        int s = g_esrc[e];
        if (hw == 0) {
            uint4 v = __ldg((const uint4*)g_xh + (size_t)s * 16 + sub);
            ACC_ROW(v);
        }
    }
#pragma unroll 1
    for (; e + 8 <= end; e += 8) {
        int4 ia = *(const int4*)(g_esrc + e);
        int4 ib = *(const int4*)(g_esrc + e + 4);
        int s0 = hw ? ia.y : ia.x;
        int s1 = hw ? ia.w : ia.z;
        int s2 = hw ? ib.y : ib.x;
        int s3 = hw ? ib.w : ib.z;
        uint4 v0 = __ldg((const uint4*)g_xh + (size_t)s0 * 16 + sub);
        uint4 v1 = __ldg((const uint4*)g_xh + (size_t)s1 * 16 + sub);
        uint4 v2 = __ldg((const uint4*)g_xh + (size_t)s2 * 16 + sub);
        uint4 v3 = __ldg((const uint4*)g_xh + (size_t)s3 * 16 + sub);
        ACC_ROW(v0); ACC_ROW(v1); ACC_ROW(v2); ACC_ROW(v3);
    }
#pragma unroll 1
    for (; e + 2 <= end; e += 2) {
        int sa = g_esrc[e], sbb = g_esrc[e + 1];
        int s = hw ? sbb : sa;
        uint4 v = __ldg((const uint4*)g_xh + (size_t)s * 16 + sub);
        ACC_ROW(v);
    }
    if (e < end) {
        int s = g_esrc[e];
        if (hw == 0) {
            uint4 v = __ldg((const uint4*)g_xh + (size_t)s * 16 + sub);
            ACC_ROW(v);
        }
    }
#undef ACC_ROW

    a0 += __shfl_xor_sync(FULL, a0, 16);
    a1 += __shfl_xor_sync(FULL, a1, 16);
    a2 += __shfl_xor_sync(FULL, a2, 16);
    a3 += __shfl_xor_sync(FULL, a3, 16);
    a4 += __shfl_xor_sync(FULL, a4, 16);
    a5 += __shfl_xor_sync(FULL, a5, 16);
    a6 += __shfl_xor_sync(FULL, a6, 16);
    a7 += __shfl_xor_sync(FULL, a7, 16);

    if (hw == 0) {
        float inv = g_invdeg[node];
        __half2 h0 = __floats2half2_rn(a0 * inv, a1 * inv);
        __half2 h1 = __floats2half2_rn(a2 * inv, a3 * inv);
        __half2 h2 = __floats2half2_rn(a4 * inv, a5 * inv);
        __half2 h3 = __floats2half2_rn(a6 * inv, a7 * inv);
        uint4 st;
        st.x = *(unsigned int*)&h0;
        st.y = *(unsigned int*)&h1;
        st.z = *(unsigned int*)&h2;
        st.w = *(unsigned int*)&h3;
        *((uint4*)g_aggh + (size_t)node * 16 + sub) = st;
    }
}

// ---------------- combine via single fp16 mma.sync: Y = relu([aggh|xh] @ W^T + b) ----------------
#define MMAF16(d, a, b0_, b1_) \
    asm volatile("mma.sync.aligned.m16n8k16.row.col.f32.f16.f16.f32 " \
                 "{%0,%1,%2,%3},{%4,%5,%6,%7},{%8,%9},{%0,%1,%2,%3};" \
                 : "+f"(d[0]), "+f"(d[1]), "+f"(d[2]), "+f"(d[3]) \
                 : "r"(a[0]), "r"(a[1]), "r"(a[2]), "r"(a[3]), "r"(b0_), "r"(b1_))

__global__ __launch_bounds__(256, 2) void combine_kernel(
    int layer, const float* __restrict__ bias, const float* __restrict__ fcw, int do_pool)
{
    const __half* __restrict__ Bh = g_Bh + layer * 128 * 256;

    __shared__ __half sA[128 * 36];
    __shared__ __half sB[128 * 36];
    __shared__ float sdot[128];

    const int tid = threadIdx.x;
    const int lane = tid & 31;
    const int warp = tid >> 5;
    const int wm = warp & 3;
    const int wn = warp >> 2;
    const int row0 = blockIdx.x * 128;
    const int gr = lane >> 2;
    const int tg2 = (lane & 3) * 2;

    if (do_pool && tid < 128) sdot[tid] = 0.f;

    float acc[2][8][4];
#pragma unroll
    for (int mt = 0; mt < 2; mt++)
#pragma unroll
        for (int nt = 0; nt < 8; nt++)
#pragma unroll
            for (int q = 0; q < 4; q++) acc[mt][nt][q] = 0.f;

#pragma unroll 1
    for (int c = 0; c < 8; c++) {
        const int k0 = c * 32;
        const bool from_x = (k0 >= 128);
        const __half* __restrict__ Asrc = from_x ? g_xh : g_aggh;
        const int kb = from_x ? (k0 - 128) : k0;
#pragma unroll
        for (int it = 0; it < 4; it++) {
            int s = tid + it * 256;
            int r = s >> 3;
            int c4 = (s & 7) * 4;
            int grow = row0 + r; if (grow >= NN) grow = NN - 1;
            *(uint2*)&sA[r * 36 + c4] = *(const uint2*)&Asrc[(size_t)grow * DD + kb + c4];
            *(uint2*)&sB[r * 36 + c4] = *(const uint2*)&Bh[r * 256 + k0 + c4];
        }
        __syncthreads();

#pragma unroll
        for (int kk = 0; kk < 32; kk += 16) {
            unsigned int a[2][4];
#pragma unroll
            for (int mt = 0; mt < 2; mt++) {
                int rb = wm * 32 + mt * 16;
                a[mt][0] = *(const unsigned int*)&sA[(rb + gr) * 36 + kk + tg2];
                a[mt][1] = *(const unsigned int*)&sA[(rb + gr + 8) * 36 + kk + tg2];
                a[mt][2] = *(const unsigned int*)&sA[(rb + gr) * 36 + kk + tg2 + 8];
                a[mt][3] = *(const unsigned int*)&sA[(rb + gr + 8) * 36 + kk + tg2 + 8];
            }
#pragma unroll
            for (int nt = 0; nt < 8; nt++) {
                int nb = wn * 64 + nt * 8 + gr;
                unsigned int b0 = *(const unsigned int*)&sB[nb * 36 + kk + tg2];
                unsigned int b1 = *(const unsigned int*)&sB[nb * 36 + kk + tg2 + 8];
#pragma unroll
                for (int mt = 0; mt < 2; mt++) {
                    MMAF16(acc[mt][nt], a[mt], b0, b1);
                }
            }
        }
        __syncthreads();
    }

    // ---- epilogue ----
    if (!do_pool) {
#pragma unroll
        for (int mt = 0; mt < 2; mt++) {
#pragma unroll
            for (int nt = 0; nt < 8; nt++) {
                int col = wn * 64 + nt * 8 + tg2;
                float b0 = bias[col], b1 = bias[col + 1];
#pragma unroll
                for (int half = 0; half < 2; half++) {
                    int row = row0 + wm * 32 + mt * 16 + gr + half * 8;
                    if (row >= NN) continue;
                    float v0 = fmaxf(acc[mt][nt][half * 2 + 0] + b0, 0.f);
                    float v1 = fmaxf(acc[mt][nt][half * 2 + 1] + b1, 0.f);
                    *(__half2*)&g_xh[(size_t)row * DD + col] = __floats2half2_rn(v0, v1);
                }
            }
        }
    } else {
#pragma unroll
        for (int mt = 0; mt < 2; mt++) {
#pragma unroll
            for (int nt = 0; nt < 8; nt++) {
                int col = wn * 64 + nt * 8 + tg2;
                float b0 = bias[col], b1 = bias[col + 1];
                float w0 = fcw[col], w1 = fcw[col + 1];
#pragma unroll
                for (int half = 0; half < 2; half++) {
                    int lr = wm * 32 + mt * 16 + gr + half * 8;
                    float v0 = fmaxf(acc[mt][nt][half * 2 + 0] + b0, 0.f);
                    float v1 = fmaxf(acc[mt][nt][half * 2 + 1] + b1, 0.f);
                    atomicAdd(&sdot[lr], v0 * w0 + v1 * w1);
                }
            }
        }
        __syncthreads();
        if (tid < 128) {
            int grow = row0 + tid;
            if (grow < NN) atomicAdd(&g_acc[g_batch[grow]], sdot[tid]);
        }
    }
}

__global__ void final_kernel(float* __restrict__ out, const float* __restrict__ fcb) {
    int g = blockIdx.x * blockDim.x + threadIdx.x;
    if (g < GG) out[g] = g_acc[g] / fmaxf(g_cnt[g], 1.f) + fcb[0];
}

// ---------------- launch ----------------
extern "C" void kernel_launch(void* const* d_in, const int* in_sizes, int n_in,
                              void* d_out, int out_size) {
    const float* x     = (const float*)d_in[0];
    const void*  ei    = d_in[1];
    const void*  batch = d_in[2];
    const float* Wl[3] = {(const float*)d_in[3], (const float*)d_in[6], (const float*)d_in[9]};
    const float* bb[3] = {(const float*)d_in[4], (const float*)d_in[7], (const float*)d_in[10]};
    const float* Wr[3] = {(const float*)d_in[5], (const float*)d_in[8], (const float*)d_in[11]};
    const float* fcw = (const float*)d_in[12];
    const float* fcb = (const float*)d_in[13];
    float* out = (float*)d_out;

    // one-time host-side infra (no device allocations)
    static cudaStream_t s_side = nullptr;
    static cudaEvent_t ev_fork = nullptr, ev_join = nullptr;
    if (!s_side) {
        cudaStreamCreateWithFlags(&s_side, cudaStreamNonBlocking);
        cudaEventCreateWithFlags(&ev_fork, cudaEventDisableTiming);
        cudaEventCreateWithFlags(&ev_join, cudaEventDisableTiming);
    }

    // prep: critical path on main stream, independent conversions forked to side stream
    init_kernel<<<NB, 256>>>(ei);
    cudaEventRecord(ev_fork, 0);
    cudaStreamWaitEvent(s_side, ev_fork, 0);
    convert_xw_kernel<<<1024, 256, 0, s_side>>>(x, Wl[0], Wr[0], Wl[1], Wr[1], Wl[2], Wr[2]);
    batch_cnt_kernel<<<NB, 256, 0, s_side>>>(batch);
    cudaEventRecord(ev_join, s_side);

    deg_hist_kernel<<<EB4, 256>>>(ei);
    scan_kernel<<<NB, 256>>>();
    place_edges_kernel<<<EB4, 256>>>(ei);
    cudaStreamWaitEvent(0, ev_join, 0);

    const int gather_blocks = (NN * 32 + 255) / 256;

    // layer 0
    gather_kernel<<<gather_blocks, 256>>>();
    combine_kernel<<<CBLK, 256>>>(0, bb[0], fcw, 0);
    // layer 1
    gather_kernel<<<gather_blocks, 256>>>();
    combine_kernel<<<CBLK, 256>>>(1, bb[1], fcw, 0);
    // layer 2: pooled dots
    gather_kernel<<<gather_blocks, 256>>>();
    combine_kernel<<<CBLK, 256>>>(2, bb[2], fcw, 1);

    final_kernel<<<(GG + 255) / 256, 256>>>(out, fcb);
}